// round 1
// baseline (speedup 1.0000x reference)
#include <cuda_runtime.h>
#include <math.h>

#define Nn 50000
#define Ee 800000
#define INF 30
#define Hh 8
#define Dd 32
#define Gg 512
#define HID 128
#define ALPHA 0.2f
#define BN_EPS 1e-5f
#define F (Hh*Dd)   // 256

// ---------------- scratch (allocation-free: __device__ globals) ----------------
__device__ float g_feat[Nn * F];     // projected features (layer1 then layer2)
__device__ float g_out [Nn * F];     // message accumulator (+bias+residual init)
__device__ float g_h1  [Nn * F];     // layer1 activation
__device__ float g_e   [Ee * Hh];    // per-edge logits, then exp values
__device__ float g_el  [Nn * Hh];
__device__ float g_er  [Nn * Hh];
__device__ float g_m   [Nn * Hh];    // segment max
__device__ float g_s   [Nn * Hh];    // segment sum
__device__ float g_gsum[Gg * Dd];
__device__ float g_gmax[Gg * Dd];

// ---------------- helpers ----------------
__device__ __forceinline__ void atomicMaxFloat(float* addr, float val) {
    int* ia = (int*)addr;
    int old = *ia;
    while (__int_as_float(old) < val) {
        int prev = atomicCAS(ia, old, __float_as_int(val));
        if (prev == old) break;
        old = prev;
    }
}

__device__ __forceinline__ float warpSum(float v) {
    #pragma unroll
    for (int o = 16; o > 0; o >>= 1) v += __shfl_down_sync(0xffffffffu, v, o);
    return v;
}

__global__ void fill_kernel(float* p, int n, float val) {
    int i = blockIdx.x * blockDim.x + threadIdx.x;
    if (i < n) p[i] = val;
}

// ---------------- layer 1 node kernel: feat = x@W1, out = b1 + x@resW1, el/er ----------------
__global__ void node1_kernel(const float* __restrict__ x,
                             const float* __restrict__ W1,
                             const float* __restrict__ resW1,
                             const float* __restrict__ b1,
                             const float* __restrict__ al1,
                             const float* __restrict__ ar1) {
    int n = blockIdx.x;
    int j = threadIdx.x;          // 0..255, h = j/32, d = j%32
    __shared__ float xr[INF];
    if (j < INF) xr[j] = x[n * INF + j];
    __syncthreads();
    float feat = 0.f, res = 0.f;
    #pragma unroll
    for (int k = 0; k < INF; k++) {
        float xv = xr[k];
        feat = fmaf(xv, W1[k * F + j], feat);
        res  = fmaf(xv, resW1[k * F + j], res);
    }
    g_feat[n * F + j] = feat;
    g_out [n * F + j] = b1[j] + res;
    float elp = warpSum(feat * al1[j]);
    float erp = warpSum(feat * ar1[j]);
    if ((j & 31) == 0) {
        int h = j >> 5;
        g_el[n * Hh + h] = elp;
        g_er[n * Hh + h] = erp;
    }
}

// ---------------- layer 2 node kernel: out = b2 + h1 (identity residual), el/er from feat2 ----------------
__global__ void node2_kernel(const float* __restrict__ b2,
                             const float* __restrict__ al2,
                             const float* __restrict__ ar2) {
    int n = blockIdx.x;
    int j = threadIdx.x;
    float feat = g_feat[n * F + j];
    g_out[n * F + j] = b2[j] + g_h1[n * F + j];
    float elp = warpSum(feat * al2[j]);
    float erp = warpSum(feat * ar2[j]);
    if ((j & 31) == 0) {
        int h = j >> 5;
        g_el[n * Hh + h] = elp;
        g_er[n * Hh + h] = erp;
    }
}

// ---------------- edge pass A: e = LeakyReLU(el[src]+er[dst]); segment max ----------------
__global__ void edgeA_kernel(const int* __restrict__ src, const int* __restrict__ dst) {
    int t = blockIdx.x * blockDim.x + threadIdx.x;
    if (t >= Ee * Hh) return;
    int e = t >> 3, h = t & 7;
    int s = src[e], d = dst[e];
    float v = g_el[s * Hh + h] + g_er[d * Hh + h];
    v = v > 0.f ? v : ALPHA * v;
    g_e[t] = v;
    atomicMaxFloat(&g_m[d * Hh + h], v);
}

// ---------------- edge pass B: ex = exp(e - m[dst]); segment sum ----------------
__global__ void edgeB_kernel(const int* __restrict__ dst) {
    int t = blockIdx.x * blockDim.x + threadIdx.x;
    if (t >= Ee * Hh) return;
    int e = t >> 3, h = t & 7;
    int d = dst[e];
    float ex = __expf(g_e[t] - g_m[d * Hh + h]);
    g_e[t] = ex;
    atomicAdd(&g_s[d * Hh + h], ex);
}

// ---------------- edge pass C: out[dst] += a * feat[src] ----------------
__global__ void edgeC_kernel(const int* __restrict__ src, const int* __restrict__ dst) {
    int e = blockIdx.x;           // one block per edge
    int j = threadIdx.x;          // 0..255
    int h = j >> 5;
    __shared__ int ss, dd;
    if (j == 0) { ss = src[e]; dd = dst[e]; }
    __syncthreads();
    int s = ss, d = dd;
    float a = g_e[e * Hh + h] / fmaxf(g_s[d * Hh + h], 1e-9f);
    atomicAdd(&g_out[d * F + j], a * g_feat[s * F + j]);
}

// ---------------- ELU: h1 = elu(out) ----------------
__global__ void elu_kernel() {
    int i = blockIdx.x * blockDim.x + threadIdx.x;
    if (i >= Nn * F) return;
    float v = g_out[i];
    g_h1[i] = v > 0.f ? v : (__expf(v) - 1.f);
}

// ---------------- SGEMM: feat = h1 @ W2   (M=50000, N=256, K=256) ----------------
#define BM 64
#define BN 64
#define BK 16
#define TM 4
#define TN 4
__global__ void gemm_kernel(const float* __restrict__ A, const float* __restrict__ B,
                            float* __restrict__ C, int M) {
    const int K = F, Ncols = F;
    __shared__ float As[BK][BM];
    __shared__ float Bs[BK][BN];
    int tid = threadIdx.x;                 // 256 threads
    int tcol = tid % (BN / TN);            // 16
    int trow = tid / (BN / TN);            // 16
    int rowBase = blockIdx.y * BM;
    int colBase = blockIdx.x * BN;
    float acc[TM][TN] = {};
    float ra[TM], rb[TN];
    for (int k0 = 0; k0 < K; k0 += BK) {
        #pragma unroll
        for (int i = 0; i < 4; i++) {
            int idx = tid + i * 256;
            int m = idx / BK, k = idx % BK;
            int gr = rowBase + m;
            As[k][m] = (gr < M) ? A[gr * K + k0 + k] : 0.f;
        }
        #pragma unroll
        for (int i = 0; i < 4; i++) {
            int idx = tid + i * 256;
            int k = idx / BN, nc = idx % BN;
            Bs[k][nc] = B[(k0 + k) * Ncols + colBase + nc];
        }
        __syncthreads();
        #pragma unroll
        for (int k = 0; k < BK; k++) {
            #pragma unroll
            for (int i = 0; i < TM; i++) ra[i] = As[k][trow * TM + i];
            #pragma unroll
            for (int jj = 0; jj < TN; jj++) rb[jj] = Bs[k][tcol * TN + jj];
            #pragma unroll
            for (int i = 0; i < TM; i++)
                #pragma unroll
                for (int jj = 0; jj < TN; jj++)
                    acc[i][jj] = fmaf(ra[i], rb[jj], acc[i][jj]);
        }
        __syncthreads();
    }
    #pragma unroll
    for (int i = 0; i < TM; i++) {
        int gr = rowBase + trow * TM + i;
        if (gr < M) {
            #pragma unroll
            for (int jj = 0; jj < TN; jj++)
                C[gr * Ncols + colBase + tcol * TN + jj] = acc[i][jj];
        }
    }
}

// ---------------- readout: h2 = mean over heads; gated sum + max per graph ----------------
__global__ void readout_kernel(const int* __restrict__ graph_ids,
                               const float* __restrict__ Ww,
                               const float* __restrict__ bw) {
    int n = blockIdx.x * 8 + (threadIdx.x >> 5);
    int d = threadIdx.x & 31;
    if (n >= Nn) return;
    float v = 0.f;
    #pragma unroll
    for (int h = 0; h < Hh; h++) v += g_out[n * F + h * Dd + d];
    v *= (1.f / Hh);
    float wl = warpSum(v * Ww[d]);
    float w;
    if (d == 0) w = 1.f / (1.f + __expf(-(wl + bw[0])));
    w = __shfl_sync(0xffffffffu, w, 0);
    int gid = graph_ids[n];
    atomicAdd(&g_gsum[gid * Dd + d], w * v);
    atomicMaxFloat(&g_gmax[gid * Dd + d], v);
}

// ---------------- MLP head: per-graph block of 128 ----------------
__global__ void mlp_kernel(const float* __restrict__ Wp1, const float* __restrict__ bp1,
                           const float* __restrict__ gamma, const float* __restrict__ beta,
                           const float* __restrict__ rm, const float* __restrict__ rv,
                           const float* __restrict__ Wp2, const float* __restrict__ bp2,
                           float* __restrict__ out) {
    int g = blockIdx.x;
    int t = threadIdx.x;      // 0..127
    __shared__ float gv[2 * Dd];
    __shared__ float red[HID];
    if (t < Dd) gv[t] = g_gsum[g * Dd + t];
    else if (t < 2 * Dd) {
        float mv = g_gmax[g * Dd + (t - Dd)];
        gv[t] = isfinite(mv) ? mv : 0.f;
    }
    __syncthreads();
    float acc = bp1[t];
    #pragma unroll
    for (int k = 0; k < 2 * Dd; k++) acc = fmaf(gv[k], Wp1[k * HID + t], acc);
    acc = fmaxf(acc, 0.f);
    acc = (acc - rm[t]) * rsqrtf(rv[t] + BN_EPS) * gamma[t] + beta[t];
    red[t] = acc * Wp2[t];
    __syncthreads();
    for (int s = 64; s > 0; s >>= 1) {
        if (t < s) red[t] += red[t + s];
        __syncthreads();
    }
    if (t == 0) out[g] = red[0] + bp2[0];
}

// ---------------- launch ----------------
extern "C" void kernel_launch(void* const* d_in, const int* in_sizes, int n_in,
                              void* d_out, int out_size) {
    const float* x     = (const float*)d_in[0];
    const int*   src   = (const int*)  d_in[1];
    const int*   dst   = (const int*)  d_in[2];
    const int*   gids  = (const int*)  d_in[3];
    const float* W1    = (const float*)d_in[4];
    const float* al1   = (const float*)d_in[5];
    const float* ar1   = (const float*)d_in[6];
    const float* b1    = (const float*)d_in[7];
    const float* resW1 = (const float*)d_in[8];
    const float* W2    = (const float*)d_in[9];
    const float* al2   = (const float*)d_in[10];
    const float* ar2   = (const float*)d_in[11];
    const float* b2    = (const float*)d_in[12];
    const float* Ww    = (const float*)d_in[13];
    const float* bw    = (const float*)d_in[14];
    const float* Wp1   = (const float*)d_in[15];
    const float* bp1   = (const float*)d_in[16];
    const float* gamma = (const float*)d_in[17];
    const float* beta  = (const float*)d_in[18];
    const float* rm    = (const float*)d_in[19];
    const float* rv    = (const float*)d_in[20];
    const float* Wp2   = (const float*)d_in[21];
    const float* bp2   = (const float*)d_in[22];
    float* out = (float*)d_out;

    float* pm; cudaGetSymbolAddress((void**)&pm, g_m);
    float* ps; cudaGetSymbolAddress((void**)&ps, g_s);
    float* pgs; cudaGetSymbolAddress((void**)&pgs, g_gsum);
    float* pgm; cudaGetSymbolAddress((void**)&pgm, g_gmax);
    float* ph1; cudaGetSymbolAddress((void**)&ph1, g_h1);
    float* pfeat; cudaGetSymbolAddress((void**)&pfeat, g_feat);

    const int NH = Nn * Hh;
    const float NEG_INF = -INFINITY;

    // ===== layer 1 =====
    fill_kernel<<<(NH + 255) / 256, 256>>>(pm, NH, NEG_INF);
    fill_kernel<<<(NH + 255) / 256, 256>>>(ps, NH, 0.f);
    node1_kernel<<<Nn, 256>>>(x, W1, resW1, b1, al1, ar1);
    edgeA_kernel<<<(Ee * Hh + 255) / 256, 256>>>(src, dst);
    edgeB_kernel<<<(Ee * Hh + 255) / 256, 256>>>(dst);
    edgeC_kernel<<<Ee, 256>>>(src, dst);
    elu_kernel<<<(Nn * F + 255) / 256, 256>>>();

    // ===== layer 2 =====
    fill_kernel<<<(NH + 255) / 256, 256>>>(pm, NH, NEG_INF);
    fill_kernel<<<(NH + 255) / 256, 256>>>(ps, NH, 0.f);
    {
        dim3 grid(F / BN, (Nn + BM - 1) / BM);
        gemm_kernel<<<grid, 256>>>(ph1, W2, pfeat, Nn);
    }
    node2_kernel<<<Nn, 256>>>(b2, al2, ar2);
    edgeA_kernel<<<(Ee * Hh + 255) / 256, 256>>>(src, dst);
    edgeB_kernel<<<(Ee * Hh + 255) / 256, 256>>>(dst);
    edgeC_kernel<<<Ee, 256>>>(src, dst);

    // ===== readout + MLP =====
    fill_kernel<<<(Gg * Dd + 255) / 256, 256>>>(pgs, Gg * Dd, 0.f);
    fill_kernel<<<(Gg * Dd + 255) / 256, 256>>>(pgm, Gg * Dd, NEG_INF);
    readout_kernel<<<(Nn + 7) / 8, 256>>>(gids, Ww, bw);
    mlp_kernel<<<Gg, HID>>>(Wp1, bp1, gamma, beta, rm, rv, Wp2, bp2, out);
}

// round 2
// speedup vs baseline: 2.4648x; 2.4648x over previous
#include <cuda_runtime.h>
#include <math.h>

#define Nn 50000
#define Ee 800000
#define INF 30
#define Hh 8
#define Dd 32
#define Gg 512
#define HID 128
#define ALPHA 0.2f
#define BN_EPS 1e-5f
#define F (Hh*Dd)   // 256

// ---------------- scratch (allocation-free: __device__ globals) ----------------
__device__ float g_feat[Nn * F];     // projected features (layer1 then layer2)
__device__ float g_out [Nn * F];     // message accumulator (+bias+residual init)
__device__ float g_h1  [Nn * F];     // layer1 activation
__device__ float g_e   [Ee * Hh];    // per-edge attention a (CSR-ordered)
__device__ float g_el  [Nn * Hh];
__device__ float g_er  [Nn * Hh];
__device__ int   g_cnt [Nn];
__device__ int   g_rowptr[Nn + 1];
__device__ int   g_cursor[Nn];
__device__ int   g_csrc[Ee];         // src node per CSR slot
__device__ float g_gsum[Gg * Dd];
__device__ float g_gmax[Gg * Dd];

// ---------------- helpers ----------------
__device__ __forceinline__ void atomicMaxFloat(float* addr, float val) {
    int* ia = (int*)addr;
    int old = *ia;
    while (__int_as_float(old) < val) {
        int prev = atomicCAS(ia, old, __float_as_int(val));
        if (prev == old) break;
        old = prev;
    }
}

__device__ __forceinline__ float warpSum(float v) {
    #pragma unroll
    for (int o = 16; o > 0; o >>= 1) v += __shfl_down_sync(0xffffffffu, v, o);
    return v;
}

__global__ void fill_kernel(float* p, int n, float val) {
    int i = blockIdx.x * blockDim.x + threadIdx.x;
    if (i < n) p[i] = val;
}
__global__ void fill_int_kernel(int* p, int n, int val) {
    int i = blockIdx.x * blockDim.x + threadIdx.x;
    if (i < n) p[i] = val;
}

// ---------------- CSR build ----------------
__global__ void hist_kernel(const int* __restrict__ dst) {
    int e = blockIdx.x * blockDim.x + threadIdx.x;
    if (e < Ee) atomicAdd(&g_cnt[dst[e]], 1);
}

// single-block exclusive scan over g_cnt -> g_rowptr, g_cursor
__global__ void scan_kernel() {
    __shared__ int sdata[1024];
    __shared__ int carry_s;
    int t = threadIdx.x;
    if (t == 0) carry_s = 0;
    __syncthreads();
    for (int base = 0; base < Nn; base += 1024) {
        int i = base + t;
        int v = (i < Nn) ? g_cnt[i] : 0;
        sdata[t] = v;
        __syncthreads();
        #pragma unroll
        for (int off = 1; off < 1024; off <<= 1) {
            int x = (t >= off) ? sdata[t - off] : 0;
            __syncthreads();
            sdata[t] += x;
            __syncthreads();
        }
        int excl = carry_s + sdata[t] - v;
        if (i < Nn) { g_rowptr[i] = excl; g_cursor[i] = excl; }
        __syncthreads();
        if (t == 1023) carry_s += sdata[1023];
        __syncthreads();
    }
    if (t == 0) g_rowptr[Nn] = carry_s;
}

__global__ void scatter_kernel(const int* __restrict__ src, const int* __restrict__ dst) {
    int e = blockIdx.x * blockDim.x + threadIdx.x;
    if (e >= Ee) return;
    int d = dst[e];
    int pos = atomicAdd(&g_cursor[d], 1);
    g_csrc[pos] = src[e];
}

// ---------------- layer 1 node kernel ----------------
__global__ void node1_kernel(const float* __restrict__ x,
                             const float* __restrict__ W1,
                             const float* __restrict__ resW1,
                             const float* __restrict__ b1,
                             const float* __restrict__ al1,
                             const float* __restrict__ ar1) {
    int n = blockIdx.x;
    int j = threadIdx.x;          // 0..255
    __shared__ float xr[INF];
    if (j < INF) xr[j] = x[n * INF + j];
    __syncthreads();
    float feat = 0.f, res = 0.f;
    #pragma unroll
    for (int k = 0; k < INF; k++) {
        float xv = xr[k];
        feat = fmaf(xv, W1[k * F + j], feat);
        res  = fmaf(xv, resW1[k * F + j], res);
    }
    g_feat[n * F + j] = feat;
    g_out [n * F + j] = b1[j] + res;
    float elp = warpSum(feat * al1[j]);
    float erp = warpSum(feat * ar1[j]);
    if ((j & 31) == 0) {
        int h = j >> 5;
        g_el[n * Hh + h] = elp;
        g_er[n * Hh + h] = erp;
    }
}

// ---------------- layer 2 node kernel ----------------
__global__ void node2_kernel(const float* __restrict__ b2,
                             const float* __restrict__ al2,
                             const float* __restrict__ ar2) {
    int n = blockIdx.x;
    int j = threadIdx.x;
    float feat = g_feat[n * F + j];
    g_out[n * F + j] = b2[j] + g_h1[n * F + j];
    float elp = warpSum(feat * al2[j]);
    float erp = warpSum(feat * ar2[j]);
    if ((j & 31) == 0) {
        int h = j >> 5;
        g_el[n * Hh + h] = elp;
        g_er[n * Hh + h] = erp;
    }
}

// ---------------- fused per-node segment softmax (no atomics) ----------------
// block = 256 threads; thread t handles head h = t&7, (edge,head) pairs p = t, t+256, ...
__global__ void edge_softmax_kernel() {
    int n = blockIdx.x;
    int t = threadIdx.x;
    int h = t & 7;
    int start = g_rowptr[n];
    int deg = g_rowptr[n + 1] - start;
    int degp = deg * 8;

    __shared__ float er_s[8];
    __shared__ float redm[8 * 8];   // [warp][head]
    __shared__ float m_s[8], s_s[8];
    if (t < 8) er_s[t] = g_er[n * 8 + t];
    __syncthreads();
    float er_h = er_s[h];

    // pass 1: max
    float mx = -INFINITY;
    for (int p = t; p < degp; p += 256) {
        int s = g_csrc[start + (p >> 3)];
        float v = g_el[s * 8 + h] + er_h;
        v = v > 0.f ? v : ALPHA * v;
        mx = fmaxf(mx, v);
    }
    mx = fmaxf(mx, __shfl_xor_sync(0xffffffffu, mx, 8));
    mx = fmaxf(mx, __shfl_xor_sync(0xffffffffu, mx, 16));
    if ((t & 31) < 8) redm[(t >> 5) * 8 + h] = mx;
    __syncthreads();
    if (t < 8) {
        float m = -INFINITY;
        #pragma unroll
        for (int w = 0; w < 8; w++) m = fmaxf(m, redm[w * 8 + t]);
        m_s[t] = m;
    }
    __syncthreads();
    float m = m_s[h];

    // pass 2: exp + sum (store raw exp to g_e, CSR-ordered, coalesced)
    float sum = 0.f;
    for (int p = t; p < degp; p += 256) {
        int s = g_csrc[start + (p >> 3)];
        float v = g_el[s * 8 + h] + er_h;
        v = v > 0.f ? v : ALPHA * v;
        float ex = __expf(v - m);
        g_e[start * 8 + p] = ex;
        sum += ex;
    }
    sum += __shfl_xor_sync(0xffffffffu, sum, 8);
    sum += __shfl_xor_sync(0xffffffffu, sum, 16);
    __syncthreads();
    if ((t & 31) < 8) redm[(t >> 5) * 8 + h] = sum;
    __syncthreads();
    if (t < 8) {
        float s = 0.f;
        #pragma unroll
        for (int w = 0; w < 8; w++) s += redm[w * 8 + t];
        s_s[t] = 1.f / fmaxf(s, 1e-9f);
    }
    __syncthreads();
    float inv = s_s[h];

    // pass 3: normalize in place (coalesced)
    for (int p = t; p < degp; p += 256) {
        g_e[start * 8 + p] *= inv;
    }
}

// ---------------- gather aggregation: out[n] += sum_e a * feat[src] ----------------
#define CHUNK 128
__global__ void edge_agg_kernel() {
    int n = blockIdx.x;
    int t = threadIdx.x;      // 0..255
    int h = t >> 5;
    int start = g_rowptr[n];
    int deg = g_rowptr[n + 1] - start;
    float acc = g_out[n * F + t];

    __shared__ int   sidx[CHUNK];
    __shared__ float sa[CHUNK * 8];

    for (int c0 = 0; c0 < deg; c0 += CHUNK) {
        int c = min(CHUNK, deg - c0);
        __syncthreads();
        if (t < c) sidx[t] = g_csrc[start + c0 + t];
        for (int q = t; q < c * 8; q += 256) sa[q] = g_e[(start + c0) * 8 + q];
        __syncthreads();
        #pragma unroll 4
        for (int e = 0; e < c; e++) {
            float a = sa[e * 8 + h];
            int s = sidx[e];
            acc = fmaf(a, g_feat[s * F + t], acc);
        }
    }
    g_out[n * F + t] = acc;
}

// ---------------- ELU ----------------
__global__ void elu_kernel() {
    int i = blockIdx.x * blockDim.x + threadIdx.x;
    if (i >= Nn * F) return;
    float v = g_out[i];
    g_h1[i] = v > 0.f ? v : (__expf(v) - 1.f);
}

// ---------------- SGEMM: feat = h1 @ W2   (M=50000, N=256, K=256) ----------------
#define BM 128
#define BN 64
#define BK 16
#define TM 8
#define TN 4
__global__ void gemm_kernel(const float* __restrict__ A, const float* __restrict__ B,
                            float* __restrict__ C, int M) {
    const int K = F, Ncols = F;
    __shared__ float As[BK][BM];
    __shared__ float Bs[BK][BN];
    int tid = threadIdx.x;                 // 256 threads
    int tcol = tid % (BN / TN);            // 16
    int trow = tid / (BN / TN);            // 16
    int rowBase = blockIdx.y * BM;
    int colBase = blockIdx.x * BN;
    float acc[TM][TN] = {};
    float ra[TM], rb[TN];

    int ar = tid >> 2;                     // 0..63 (rows ar, ar+64)
    int ac = (tid & 3) * 4;                // float4 col in BK
    int bk = tid >> 4;                     // 0..15
    int bc = (tid & 15) * 4;               // float4 col in BN

    for (int k0 = 0; k0 < K; k0 += BK) {
        #pragma unroll
        for (int half = 0; half < 2; half++) {
            int m = ar + half * 64;
            int gr = rowBase + m;
            float4 va = (gr < M) ? *(const float4*)&A[gr * K + k0 + ac]
                                 : make_float4(0.f, 0.f, 0.f, 0.f);
            As[ac + 0][m] = va.x;
            As[ac + 1][m] = va.y;
            As[ac + 2][m] = va.z;
            As[ac + 3][m] = va.w;
        }
        *(float4*)&Bs[bk][bc] = *(const float4*)&B[(k0 + bk) * Ncols + colBase + bc];
        __syncthreads();
        #pragma unroll
        for (int k = 0; k < BK; k++) {
            #pragma unroll
            for (int i = 0; i < TM; i++) ra[i] = As[k][trow * TM + i];
            #pragma unroll
            for (int j = 0; j < TN; j++) rb[j] = Bs[k][tcol * TN + j];
            #pragma unroll
            for (int i = 0; i < TM; i++)
                #pragma unroll
                for (int j = 0; j < TN; j++)
                    acc[i][j] = fmaf(ra[i], rb[j], acc[i][j]);
        }
        __syncthreads();
    }
    #pragma unroll
    for (int i = 0; i < TM; i++) {
        int gr = rowBase + trow * TM + i;
        if (gr < M) {
            float4 v = make_float4(acc[i][0], acc[i][1], acc[i][2], acc[i][3]);
            *(float4*)&C[gr * Ncols + colBase + tcol * TN] = v;
        }
    }
}

// ---------------- readout ----------------
__global__ void readout_kernel(const int* __restrict__ graph_ids,
                               const float* __restrict__ Ww,
                               const float* __restrict__ bw) {
    int n = blockIdx.x * 8 + (threadIdx.x >> 5);
    int d = threadIdx.x & 31;
    if (n >= Nn) return;
    float v = 0.f;
    #pragma unroll
    for (int h = 0; h < Hh; h++) v += g_out[n * F + h * Dd + d];
    v *= (1.f / Hh);
    float wl = warpSum(v * Ww[d]);
    float w;
    if (d == 0) w = 1.f / (1.f + __expf(-(wl + bw[0])));
    w = __shfl_sync(0xffffffffu, w, 0);
    int gid = graph_ids[n];
    atomicAdd(&g_gsum[gid * Dd + d], w * v);
    atomicMaxFloat(&g_gmax[gid * Dd + d], v);
}

// ---------------- MLP head ----------------
__global__ void mlp_kernel(const float* __restrict__ Wp1, const float* __restrict__ bp1,
                           const float* __restrict__ gamma, const float* __restrict__ beta,
                           const float* __restrict__ rm, const float* __restrict__ rv,
                           const float* __restrict__ Wp2, const float* __restrict__ bp2,
                           float* __restrict__ out) {
    int g = blockIdx.x;
    int t = threadIdx.x;      // 0..127
    __shared__ float gv[2 * Dd];
    __shared__ float red[HID];
    if (t < Dd) gv[t] = g_gsum[g * Dd + t];
    else if (t < 2 * Dd) {
        float mv = g_gmax[g * Dd + (t - Dd)];
        gv[t] = isfinite(mv) ? mv : 0.f;
    }
    __syncthreads();
    float acc = bp1[t];
    #pragma unroll
    for (int k = 0; k < 2 * Dd; k++) acc = fmaf(gv[k], Wp1[k * HID + t], acc);
    acc = fmaxf(acc, 0.f);
    acc = (acc - rm[t]) * rsqrtf(rv[t] + BN_EPS) * gamma[t] + beta[t];
    red[t] = acc * Wp2[t];
    __syncthreads();
    for (int s = 64; s > 0; s >>= 1) {
        if (t < s) red[t] += red[t + s];
        __syncthreads();
    }
    if (t == 0) out[g] = red[0] + bp2[0];
}

// ---------------- launch ----------------
extern "C" void kernel_launch(void* const* d_in, const int* in_sizes, int n_in,
                              void* d_out, int out_size) {
    const float* x     = (const float*)d_in[0];
    const int*   src   = (const int*)  d_in[1];
    const int*   dst   = (const int*)  d_in[2];
    const int*   gids  = (const int*)  d_in[3];
    const float* W1    = (const float*)d_in[4];
    const float* al1   = (const float*)d_in[5];
    const float* ar1   = (const float*)d_in[6];
    const float* b1    = (const float*)d_in[7];
    const float* resW1 = (const float*)d_in[8];
    const float* W2    = (const float*)d_in[9];
    const float* al2   = (const float*)d_in[10];
    const float* ar2   = (const float*)d_in[11];
    const float* b2    = (const float*)d_in[12];
    const float* Ww    = (const float*)d_in[13];
    const float* bw    = (const float*)d_in[14];
    const float* Wp1   = (const float*)d_in[15];
    const float* bp1   = (const float*)d_in[16];
    const float* gamma = (const float*)d_in[17];
    const float* beta  = (const float*)d_in[18];
    const float* rm    = (const float*)d_in[19];
    const float* rv    = (const float*)d_in[20];
    const float* Wp2   = (const float*)d_in[21];
    const float* bp2   = (const float*)d_in[22];
    float* out = (float*)d_out;

    int* pcnt;  cudaGetSymbolAddress((void**)&pcnt, g_cnt);
    float* pgs; cudaGetSymbolAddress((void**)&pgs, g_gsum);
    float* pgm; cudaGetSymbolAddress((void**)&pgm, g_gmax);
    float* ph1; cudaGetSymbolAddress((void**)&ph1, g_h1);
    float* pfeat; cudaGetSymbolAddress((void**)&pfeat, g_feat);

    const float NEG_INF = -INFINITY;

    // ===== CSR build (by dst) =====
    fill_int_kernel<<<(Nn + 255) / 256, 256>>>(pcnt, Nn, 0);
    hist_kernel<<<(Ee + 255) / 256, 256>>>(dst);
    scan_kernel<<<1, 1024>>>();
    scatter_kernel<<<(Ee + 255) / 256, 256>>>(src, dst);

    // ===== layer 1 =====
    node1_kernel<<<Nn, 256>>>(x, W1, resW1, b1, al1, ar1);
    edge_softmax_kernel<<<Nn, 256>>>();
    edge_agg_kernel<<<Nn, 256>>>();
    elu_kernel<<<(Nn * F + 255) / 256, 256>>>();

    // ===== layer 2 =====
    {
        dim3 grid(F / BN, (Nn + BM - 1) / BM);
        gemm_kernel<<<grid, 256>>>(ph1, W2, pfeat, Nn);
    }
    node2_kernel<<<Nn, 256>>>(b2, al2, ar2);
    edge_softmax_kernel<<<Nn, 256>>>();
    edge_agg_kernel<<<Nn, 256>>>();

    // ===== readout + MLP =====
    fill_kernel<<<(Gg * Dd + 255) / 256, 256>>>(pgs, Gg * Dd, 0.f);
    fill_kernel<<<(Gg * Dd + 255) / 256, 256>>>(pgm, Gg * Dd, NEG_INF);
    readout_kernel<<<(Nn + 7) / 8, 256>>>(gids, Ww, bw);
    mlp_kernel<<<Gg, HID>>>(Wp1, bp1, gamma, beta, rm, rv, Wp2, bp2, out);
}

// round 3
// speedup vs baseline: 4.8537x; 1.9692x over previous
#include <cuda_runtime.h>
#include <math.h>

#define Nn 50000
#define Ee 800000
#define INF 30
#define Hh 8
#define Dd 32
#define Gg 512
#define HID 128
#define ALPHA 0.2f
#define BN_EPS 1e-5f
#define F (Hh*Dd)   // 256

// ---------------- scratch (allocation-free: __device__ globals) ----------------
__device__ float g_feat[Nn * F];     // projected features (layer1 then layer2)
__device__ float g_out [Nn * F];     // layer1: b1 + x@resW1 (base); layer2 result
__device__ float g_h1  [Nn * F];     // layer1 activation
__device__ float g_el  [Nn * Hh];
__device__ float g_er  [Nn * Hh];
__device__ int   g_cnt [Nn];
__device__ int   g_rowptr[Nn + 1];
__device__ int   g_cursor[Nn];
__device__ int   g_csrc[Ee];         // src node per CSR slot
__device__ int   g_bsum[256];
__device__ float g_gsum[Gg * Dd];
__device__ float g_gmax[Gg * Dd];

// ---------------- helpers ----------------
__device__ __forceinline__ void atomicMaxFloat(float* addr, float val) {
    int* ia = (int*)addr;
    int old = *ia;
    while (__int_as_float(old) < val) {
        int prev = atomicCAS(ia, old, __float_as_int(val));
        if (prev == old) break;
        old = prev;
    }
}

__device__ __forceinline__ float warpSum(float v) {
    #pragma unroll
    for (int o = 16; o > 0; o >>= 1) v += __shfl_down_sync(0xffffffffu, v, o);
    return v;
}

__global__ void fill_kernel(float* p, int n, float val) {
    int i = blockIdx.x * blockDim.x + threadIdx.x;
    if (i < n) p[i] = val;
}
__global__ void fill_int_kernel(int* p, int n, int val) {
    int i = blockIdx.x * blockDim.x + threadIdx.x;
    if (i < n) p[i] = val;
}

// ---------------- CSR build ----------------
__global__ void hist_kernel(const int* __restrict__ dst) {
    int e = blockIdx.x * blockDim.x + threadIdx.x;
    if (e < Ee) atomicAdd(&g_cnt[dst[e]], 1);
}

// multi-block scan: per-block exclusive + block sums
__global__ void scan1_kernel() {
    __shared__ int sd[256];
    int t = threadIdx.x;
    int i = blockIdx.x * 256 + t;
    int v = (i < Nn) ? g_cnt[i] : 0;
    sd[t] = v;
    __syncthreads();
    #pragma unroll
    for (int off = 1; off < 256; off <<= 1) {
        int x = (t >= off) ? sd[t - off] : 0;
        __syncthreads();
        sd[t] += x;
        __syncthreads();
    }
    if (i < Nn) g_rowptr[i] = sd[t] - v;        // block-local exclusive
    if (t == 255) g_bsum[blockIdx.x] = sd[255]; // block total
}

__global__ void scan2_kernel(int nb) {
    __shared__ int sd[256];
    int t = threadIdx.x;
    int v = (t < nb) ? g_bsum[t] : 0;
    sd[t] = v;
    __syncthreads();
    #pragma unroll
    for (int off = 1; off < 256; off <<= 1) {
        int x = (t >= off) ? sd[t - off] : 0;
        __syncthreads();
        sd[t] += x;
        __syncthreads();
    }
    if (t < nb) g_bsum[t] = sd[t] - v;          // exclusive
    if (t == 0) g_rowptr[Nn] = Ee;
}

__global__ void scan3_kernel() {
    int i = blockIdx.x * 256 + threadIdx.x;
    if (i < Nn) {
        int r = g_rowptr[i] + g_bsum[blockIdx.x];
        g_rowptr[i] = r;
        g_cursor[i] = r;
    }
}

__global__ void scatter_kernel(const int* __restrict__ src, const int* __restrict__ dst) {
    int e = blockIdx.x * blockDim.x + threadIdx.x;
    if (e >= Ee) return;
    int d = dst[e];
    int pos = atomicAdd(&g_cursor[d], 1);
    g_csrc[pos] = src[e];
}

// ---------------- layer 1 node kernel (register-cached W columns, node strip) ----------------
#define NPB 64
__global__ void node1_kernel(const float* __restrict__ x,
                             const float* __restrict__ W1,
                             const float* __restrict__ resW1,
                             const float* __restrict__ b1,
                             const float* __restrict__ al1,
                             const float* __restrict__ ar1) {
    int j = threadIdx.x;                 // output column 0..255
    int base = blockIdx.x * NPB;
    int cnt = min(NPB, Nn - base);
    __shared__ float xs[NPB * INF];
    for (int q = j; q < cnt * INF; q += 256) xs[q] = x[base * INF + q];

    float w1r[INF], wrr[INF];
    #pragma unroll
    for (int k = 0; k < INF; k++) {
        w1r[k] = W1[k * F + j];
        wrr[k] = resW1[k * F + j];
    }
    float a_l = al1[j], a_r = ar1[j], bj = b1[j];
    __syncthreads();

    for (int u = 0; u < cnt; u++) {
        int n = base + u;
        float feat = 0.f, res = 0.f;
        #pragma unroll
        for (int k = 0; k < INF; k++) {
            float xv = xs[u * INF + k];
            feat = fmaf(xv, w1r[k], feat);
            res  = fmaf(xv, wrr[k], res);
        }
        g_feat[n * F + j] = feat;
        g_out [n * F + j] = bj + res;
        float elp = warpSum(feat * a_l);
        float erp = warpSum(feat * a_r);
        if ((j & 31) == 0) {
            int h = j >> 5;
            g_el[n * Hh + h] = elp;
            g_er[n * Hh + h] = erp;
        }
    }
}

// ---------------- layer 2 el/er kernel ----------------
__global__ void node2el_kernel(const float* __restrict__ al2,
                               const float* __restrict__ ar2) {
    int n = blockIdx.x;
    int j = threadIdx.x;
    float feat = g_feat[n * F + j];
    float elp = warpSum(feat * al2[j]);
    float erp = warpSum(feat * ar2[j]);
    if ((j & 31) == 0) {
        int h = j >> 5;
        g_el[n * Hh + h] = elp;
        g_er[n * Hh + h] = erp;
    }
}

// ---------------- fused softmax + gather aggregation ----------------
// block = 64 threads, one dst node; thread t covers feats [4t, 4t+4), head h = t>>3.
// Computes sum(ex) and sum(ex*feat) in one pass, normalizes at end (softmax identity).
template<bool LAYER1>
__global__ void agg_kernel(const float* __restrict__ b2) {
    int n = blockIdx.x;
    int t = threadIdx.x;          // 0..63
    int h = t >> 3;
    float er_h = g_er[n * Hh + h];
    int start = g_rowptr[n];
    int end   = g_rowptr[n + 1];

    float ax = 0.f, ay = 0.f, az = 0.f, aw = 0.f;
    float ssum = 0.f;
    #pragma unroll 4
    for (int e = start; e < end; e++) {
        int s = g_csrc[e];
        float el = g_el[s * Hh + h];
        float v = el + er_h;
        v = v > 0.f ? v : ALPHA * v;
        float ex = __expf(v);
        ssum += ex;
        float4 f = *(const float4*)&g_feat[s * F + t * 4];
        ax = fmaf(ex, f.x, ax);
        ay = fmaf(ex, f.y, ay);
        az = fmaf(ex, f.z, az);
        aw = fmaf(ex, f.w, aw);
    }
    float inv = 1.f / fmaxf(ssum, 1e-9f);

    if (LAYER1) {
        float4 base = *(const float4*)&g_out[n * F + t * 4];   // b1 + x@resW1
        float rx = base.x + ax * inv;
        float ry = base.y + ay * inv;
        float rz = base.z + az * inv;
        float rw = base.w + aw * inv;
        // ELU
        rx = rx > 0.f ? rx : (__expf(rx) - 1.f);
        ry = ry > 0.f ? ry : (__expf(ry) - 1.f);
        rz = rz > 0.f ? rz : (__expf(rz) - 1.f);
        rw = rw > 0.f ? rw : (__expf(rw) - 1.f);
        float4 r = make_float4(rx, ry, rz, rw);
        *(float4*)&g_h1[n * F + t * 4] = r;
    } else {
        float4 hb = *(const float4*)&g_h1[n * F + t * 4];
        float4 bb = *(const float4*)&b2[t * 4];
        float4 r = make_float4(hb.x + bb.x + ax * inv,
                               hb.y + bb.y + ay * inv,
                               hb.z + bb.z + az * inv,
                               hb.w + bb.w + aw * inv);
        *(float4*)&g_out[n * F + t * 4] = r;
    }
}

// ---------------- SGEMM: feat = h1 @ W2   (M=50000, N=256, K=256) ----------------
#define GBM 128
#define GBN 128
#define GBK 16
#define GTM 8
#define GTN 8
__global__ void gemm_kernel(const float* __restrict__ A, const float* __restrict__ B,
                            float* __restrict__ C, int M) {
    const int K = F, Ncols = F;
    __shared__ float As[GBK][GBM + 4];
    __shared__ float Bs[GBK][GBN];
    int tid = threadIdx.x;                 // 256 threads
    int trow = tid >> 4;                   // 0..15
    int tcol = tid & 15;                   // 0..15
    int rowBase = blockIdx.y * GBM;
    int colBase = blockIdx.x * GBN;
    float acc[GTM][GTN] = {};
    float ra[GTM], rb[GTN];

    int arow = tid >> 2;                   // 0..63 (rows arow, arow+64)
    int aq = (tid & 3) * 4;                // float4 start col in BK
    // B: 512 float4 slots, 2 per thread: idx = tid, tid+256
    int bk0 = tid >> 5;                    // 0..7
    int bc0 = (tid & 31) * 4;

    for (int k0 = 0; k0 < K; k0 += GBK) {
        #pragma unroll
        for (int half = 0; half < 2; half++) {
            int m = arow + half * 64;
            int gr = rowBase + m;
            float4 va = (gr < M) ? *(const float4*)&A[gr * K + k0 + aq]
                                 : make_float4(0.f, 0.f, 0.f, 0.f);
            As[aq + 0][m] = va.x;
            As[aq + 1][m] = va.y;
            As[aq + 2][m] = va.z;
            As[aq + 3][m] = va.w;
        }
        #pragma unroll
        for (int half = 0; half < 2; half++) {
            int k = bk0 + half * 8;
            *(float4*)&Bs[k][bc0] = *(const float4*)&B[(k0 + k) * Ncols + colBase + bc0];
        }
        __syncthreads();
        #pragma unroll
        for (int k = 0; k < GBK; k++) {
            #pragma unroll
            for (int i = 0; i < GTM; i++) ra[i] = As[k][trow * GTM + i];
            #pragma unroll
            for (int j = 0; j < GTN; j++) rb[j] = Bs[k][tcol * GTN + j];
            #pragma unroll
            for (int i = 0; i < GTM; i++)
                #pragma unroll
                for (int j = 0; j < GTN; j++)
                    acc[i][j] = fmaf(ra[i], rb[j], acc[i][j]);
        }
        __syncthreads();
    }
    #pragma unroll
    for (int i = 0; i < GTM; i++) {
        int gr = rowBase + trow * GTM + i;
        if (gr < M) {
            float4 v0 = make_float4(acc[i][0], acc[i][1], acc[i][2], acc[i][3]);
            float4 v1 = make_float4(acc[i][4], acc[i][5], acc[i][6], acc[i][7]);
            *(float4*)&C[gr * Ncols + colBase + tcol * GTN]     = v0;
            *(float4*)&C[gr * Ncols + colBase + tcol * GTN + 4] = v1;
        }
    }
}

// ---------------- readout ----------------
__global__ void readout_kernel(const int* __restrict__ graph_ids,
                               const float* __restrict__ Ww,
                               const float* __restrict__ bw) {
    int n = blockIdx.x * 8 + (threadIdx.x >> 5);
    int d = threadIdx.x & 31;
    if (n >= Nn) return;
    float v = 0.f;
    #pragma unroll
    for (int h = 0; h < Hh; h++) v += g_out[n * F + h * Dd + d];
    v *= (1.f / Hh);
    float wl = warpSum(v * Ww[d]);
    float w;
    if (d == 0) w = 1.f / (1.f + __expf(-(wl + bw[0])));
    w = __shfl_sync(0xffffffffu, w, 0);
    int gid = graph_ids[n];
    atomicAdd(&g_gsum[gid * Dd + d], w * v);
    atomicMaxFloat(&g_gmax[gid * Dd + d], v);
}

// ---------------- MLP head ----------------
__global__ void mlp_kernel(const float* __restrict__ Wp1, const float* __restrict__ bp1,
                           const float* __restrict__ gamma, const float* __restrict__ beta,
                           const float* __restrict__ rm, const float* __restrict__ rv,
                           const float* __restrict__ Wp2, const float* __restrict__ bp2,
                           float* __restrict__ out) {
    int g = blockIdx.x;
    int t = threadIdx.x;      // 0..127
    __shared__ float gv[2 * Dd];
    __shared__ float red[HID];
    if (t < Dd) gv[t] = g_gsum[g * Dd + t];
    else if (t < 2 * Dd) {
        float mv = g_gmax[g * Dd + (t - Dd)];
        gv[t] = isfinite(mv) ? mv : 0.f;
    }
    __syncthreads();
    float acc = bp1[t];
    #pragma unroll
    for (int k = 0; k < 2 * Dd; k++) acc = fmaf(gv[k], Wp1[k * HID + t], acc);
    acc = fmaxf(acc, 0.f);
    acc = (acc - rm[t]) * rsqrtf(rv[t] + BN_EPS) * gamma[t] + beta[t];
    red[t] = acc * Wp2[t];
    __syncthreads();
    for (int s = 64; s > 0; s >>= 1) {
        if (t < s) red[t] += red[t + s];
        __syncthreads();
    }
    if (t == 0) out[g] = red[0] + bp2[0];
}

// ---------------- launch ----------------
extern "C" void kernel_launch(void* const* d_in, const int* in_sizes, int n_in,
                              void* d_out, int out_size) {
    const float* x     = (const float*)d_in[0];
    const int*   src   = (const int*)  d_in[1];
    const int*   dst   = (const int*)  d_in[2];
    const int*   gids  = (const int*)  d_in[3];
    const float* W1    = (const float*)d_in[4];
    const float* al1   = (const float*)d_in[5];
    const float* ar1   = (const float*)d_in[6];
    const float* b1    = (const float*)d_in[7];
    const float* resW1 = (const float*)d_in[8];
    const float* W2    = (const float*)d_in[9];
    const float* al2   = (const float*)d_in[10];
    const float* ar2   = (const float*)d_in[11];
    const float* b2    = (const float*)d_in[12];
    const float* Ww    = (const float*)d_in[13];
    const float* bw    = (const float*)d_in[14];
    const float* Wp1   = (const float*)d_in[15];
    const float* bp1   = (const float*)d_in[16];
    const float* gamma = (const float*)d_in[17];
    const float* beta  = (const float*)d_in[18];
    const float* rm    = (const float*)d_in[19];
    const float* rv    = (const float*)d_in[20];
    const float* Wp2   = (const float*)d_in[21];
    const float* bp2   = (const float*)d_in[22];
    float* out = (float*)d_out;

    int* pcnt;  cudaGetSymbolAddress((void**)&pcnt, g_cnt);
    float* pgs; cudaGetSymbolAddress((void**)&pgs, g_gsum);
    float* pgm; cudaGetSymbolAddress((void**)&pgm, g_gmax);
    float* ph1; cudaGetSymbolAddress((void**)&ph1, g_h1);
    float* pfeat; cudaGetSymbolAddress((void**)&pfeat, g_feat);

    const float NEG_INF = -INFINITY;
    const int NB = (Nn + 255) / 256;   // 196 scan blocks

    // ===== CSR build (by dst) =====
    fill_int_kernel<<<NB, 256>>>(pcnt, Nn, 0);
    hist_kernel<<<(Ee + 255) / 256, 256>>>(dst);
    scan1_kernel<<<NB, 256>>>();
    scan2_kernel<<<1, 256>>>(NB);
    scan3_kernel<<<NB, 256>>>();
    scatter_kernel<<<(Ee + 255) / 256, 256>>>(src, dst);

    // ===== layer 1 =====
    node1_kernel<<<(Nn + NPB - 1) / NPB, 256>>>(x, W1, resW1, b1, al1, ar1);
    agg_kernel<true><<<Nn, 64>>>(nullptr);

    // ===== layer 2 =====
    {
        dim3 grid(F / GBN, (Nn + GBM - 1) / GBM);
        gemm_kernel<<<grid, 256>>>(ph1, W2, pfeat, Nn);
    }
    node2el_kernel<<<Nn, 256>>>(al2, ar2);
    agg_kernel<false><<<Nn, 64>>>(b2);

    // ===== readout + MLP =====
    fill_kernel<<<(Gg * Dd + 255) / 256, 256>>>(pgs, Gg * Dd, 0.f);
    fill_kernel<<<(Gg * Dd + 255) / 256, 256>>>(pgm, Gg * Dd, NEG_INF);
    readout_kernel<<<(Nn + 7) / 8, 256>>>(gids, Ww, bw);
    mlp_kernel<<<Gg, HID>>>(Wp1, bp1, gamma, beta, rm, rv, Wp2, bp2, out);
}

// round 5
// speedup vs baseline: 5.4069x; 1.1140x over previous
#include <cuda_runtime.h>
#include <cuda_bf16.h>
#include <math.h>
#include <cstdint>

#define Nn 50000
#define Ee 800000
#define INF 30
#define Hh 8
#define Dd 32
#define Gg 512
#define HID 128
#define ALPHA 0.2f
#define BN_EPS 1e-5f
#define F (Hh*Dd)   // 256

// ---------------- scratch (allocation-free: __device__ globals) ----------------
__device__ __nv_bfloat16 g_featb[Nn * F];  // projected features (bf16, gather side)
__device__ float g_out [Nn * F];     // layer1: b1 + x@resW1 (base); layer2 result
__device__ float g_h1  [Nn * F];     // layer1 activation (fp32, GEMM A input)
__device__ float g_el  [Nn * Hh];
__device__ float g_er  [Nn * Hh];
__device__ int   g_cnt [Nn];
__device__ int   g_rowptr[Nn + 1];
__device__ int   g_cursor[Nn];
__device__ int   g_csrc[Ee];         // src node per CSR slot
__device__ int   g_bsum[256];
__device__ float g_gsum[Gg * Dd];
__device__ float g_gmax[Gg * Dd];

// ---------------- helpers ----------------
__device__ __forceinline__ void atomicMaxFloat(float* addr, float val) {
    int* ia = (int*)addr;
    int old = *ia;
    while (__int_as_float(old) < val) {
        int prev = atomicCAS(ia, old, __float_as_int(val));
        if (prev == old) break;
        old = prev;
    }
}

__device__ __forceinline__ float warpSum(float v) {
    #pragma unroll
    for (int o = 16; o > 0; o >>= 1) v += __shfl_down_sync(0xffffffffu, v, o);
    return v;
}

__global__ void fill_kernel(float* p, int n, float val) {
    int i = blockIdx.x * blockDim.x + threadIdx.x;
    if (i < n) p[i] = val;
}
__global__ void fill_int_kernel(int* p, int n, int val) {
    int i = blockIdx.x * blockDim.x + threadIdx.x;
    if (i < n) p[i] = val;
}

// ---------------- CSR build ----------------
__global__ void hist_kernel(const int* __restrict__ dst) {
    int e = blockIdx.x * blockDim.x + threadIdx.x;
    if (e < Ee) atomicAdd(&g_cnt[dst[e]], 1);
}

__global__ void scan1_kernel() {
    __shared__ int sd[256];
    int t = threadIdx.x;
    int i = blockIdx.x * 256 + t;
    int v = (i < Nn) ? g_cnt[i] : 0;
    sd[t] = v;
    __syncthreads();
    #pragma unroll
    for (int off = 1; off < 256; off <<= 1) {
        int x = (t >= off) ? sd[t - off] : 0;
        __syncthreads();
        sd[t] += x;
        __syncthreads();
    }
    if (i < Nn) g_rowptr[i] = sd[t] - v;
    if (t == 255) g_bsum[blockIdx.x] = sd[255];
}

__global__ void scan2_kernel(int nb) {
    __shared__ int sd[256];
    int t = threadIdx.x;
    int v = (t < nb) ? g_bsum[t] : 0;
    sd[t] = v;
    __syncthreads();
    #pragma unroll
    for (int off = 1; off < 256; off <<= 1) {
        int x = (t >= off) ? sd[t - off] : 0;
        __syncthreads();
        sd[t] += x;
        __syncthreads();
    }
    if (t < nb) g_bsum[t] = sd[t] - v;
    if (t == 0) g_rowptr[Nn] = Ee;
}

__global__ void scan3_kernel() {
    int i = blockIdx.x * 256 + threadIdx.x;
    if (i < Nn) {
        int r = g_rowptr[i] + g_bsum[blockIdx.x];
        g_rowptr[i] = r;
        g_cursor[i] = r;
    }
}

__global__ void scatter_kernel(const int* __restrict__ src, const int* __restrict__ dst) {
    int e = blockIdx.x * blockDim.x + threadIdx.x;
    if (e >= Ee) return;
    int d = dst[e];
    int pos = atomicAdd(&g_cursor[d], 1);
    g_csrc[pos] = src[e];
}

// ---------------- layer 1 node kernel (register-cached W columns, node strip) ----------------
#define NPB 64
__global__ void node1_kernel(const float* __restrict__ x,
                             const float* __restrict__ W1,
                             const float* __restrict__ resW1,
                             const float* __restrict__ b1,
                             const float* __restrict__ al1,
                             const float* __restrict__ ar1) {
    int j = threadIdx.x;                 // output column 0..255
    int base = blockIdx.x * NPB;
    int cnt = min(NPB, Nn - base);
    __shared__ float xs[NPB * INF];
    for (int q = j; q < cnt * INF; q += 256) xs[q] = x[base * INF + q];

    float w1r[INF], wrr[INF];
    #pragma unroll
    for (int k = 0; k < INF; k++) {
        w1r[k] = W1[k * F + j];
        wrr[k] = resW1[k * F + j];
    }
    float a_l = al1[j], a_r = ar1[j], bj = b1[j];
    __syncthreads();

    for (int u = 0; u < cnt; u++) {
        int n = base + u;
        float feat = 0.f, res = 0.f;
        #pragma unroll
        for (int k = 0; k < INF; k++) {
            float xv = xs[u * INF + k];
            feat = fmaf(xv, w1r[k], feat);
            res  = fmaf(xv, wrr[k], res);
        }
        g_featb[n * F + j] = __float2bfloat16(feat);
        g_out  [n * F + j] = bj + res;
        float elp = warpSum(feat * a_l);
        float erp = warpSum(feat * a_r);
        if ((j & 31) == 0) {
            int h = j >> 5;
            g_el[n * Hh + h] = elp;
            g_er[n * Hh + h] = erp;
        }
    }
}

// ---------------- layer 2 el/er kernel (reads bf16 feat) ----------------
__global__ void node2el_kernel(const float* __restrict__ al2,
                               const float* __restrict__ ar2) {
    int n = blockIdx.x;
    int j = threadIdx.x;
    float feat = __bfloat162float(g_featb[n * F + j]);
    float elp = warpSum(feat * al2[j]);
    float erp = warpSum(feat * ar2[j]);
    if ((j & 31) == 0) {
        int h = j >> 5;
        g_el[n * Hh + h] = elp;
        g_er[n * Hh + h] = erp;
    }
}

// ---------------- fused softmax + gather aggregation (bf16 feats) ----------------
// block = 64 threads, one dst node; thread t covers feats [4t, 4t+4), head h = t>>3.
template<bool LAYER1>
__global__ void agg_kernel(const float* __restrict__ b2) {
    int n = blockIdx.x;
    int t = threadIdx.x;          // 0..63
    int h = t >> 3;
    float er_h = g_er[n * Hh + h];
    int start = g_rowptr[n];
    int end   = g_rowptr[n + 1];

    float ax = 0.f, ay = 0.f, az = 0.f, aw = 0.f;
    float ssum = 0.f;
    #pragma unroll 4
    for (int e = start; e < end; e++) {
        int s = g_csrc[e];
        float v = g_el[s * Hh + h] + er_h;
        v = v > 0.f ? v : ALPHA * v;
        float ex = __expf(v);
        ssum += ex;
        uint2 u = *(const uint2*)&g_featb[s * F + t * 4];
        float2 f01 = __bfloat1622float2(*reinterpret_cast<const __nv_bfloat162*>(&u.x));
        float2 f23 = __bfloat1622float2(*reinterpret_cast<const __nv_bfloat162*>(&u.y));
        ax = fmaf(ex, f01.x, ax);
        ay = fmaf(ex, f01.y, ay);
        az = fmaf(ex, f23.x, az);
        aw = fmaf(ex, f23.y, aw);
    }
    float inv = 1.f / fmaxf(ssum, 1e-9f);

    if (LAYER1) {
        float4 base = *(const float4*)&g_out[n * F + t * 4];   // b1 + x@resW1
        float rx = base.x + ax * inv;
        float ry = base.y + ay * inv;
        float rz = base.z + az * inv;
        float rw = base.w + aw * inv;
        rx = rx > 0.f ? rx : (__expf(rx) - 1.f);
        ry = ry > 0.f ? ry : (__expf(ry) - 1.f);
        rz = rz > 0.f ? rz : (__expf(rz) - 1.f);
        rw = rw > 0.f ? rw : (__expf(rw) - 1.f);
        *(float4*)&g_h1[n * F + t * 4] = make_float4(rx, ry, rz, rw);
    } else {
        float4 hb = *(const float4*)&g_h1[n * F + t * 4];
        float4 bb = *(const float4*)&b2[t * 4];
        *(float4*)&g_out[n * F + t * 4] = make_float4(hb.x + bb.x + ax * inv,
                                                      hb.y + bb.y + ay * inv,
                                                      hb.z + bb.z + az * inv,
                                                      hb.w + bb.w + aw * inv);
    }
}

// ---------------- SGEMM: featb = bf16(h1 @ W2)   (M=50000, N=256, K=256) ----------------
#define GBM 128
#define GBN 128
#define GBK 16
#define GTM 8
#define GTN 8
__global__ void gemm_kernel(const float* __restrict__ A, const float* __restrict__ B,
                            __nv_bfloat16* __restrict__ C, int M) {
    const int K = F, Ncols = F;
    __shared__ float As[GBK][GBM + 4];
    __shared__ float Bs[GBK][GBN];
    int tid = threadIdx.x;                 // 256 threads
    int trow = tid >> 4;                   // 0..15
    int tcol = tid & 15;                   // 0..15
    int rowBase = blockIdx.y * GBM;
    int colBase = blockIdx.x * GBN;
    float acc[GTM][GTN] = {};
    float ra[GTM], rb[GTN];

    int arow = tid >> 2;                   // 0..63 (rows arow, arow+64)
    int aq = (tid & 3) * 4;                // float4 start col in BK
    int bk0 = tid >> 5;                    // 0..7
    int bc0 = (tid & 31) * 4;

    for (int k0 = 0; k0 < K; k0 += GBK) {
        #pragma unroll
        for (int half = 0; half < 2; half++) {
            int m = arow + half * 64;
            int gr = rowBase + m;
            float4 va = (gr < M) ? *(const float4*)&A[gr * K + k0 + aq]
                                 : make_float4(0.f, 0.f, 0.f, 0.f);
            As[aq + 0][m] = va.x;
            As[aq + 1][m] = va.y;
            As[aq + 2][m] = va.z;
            As[aq + 3][m] = va.w;
        }
        #pragma unroll
        for (int half = 0; half < 2; half++) {
            int k = bk0 + half * 8;
            *(float4*)&Bs[k][bc0] = *(const float4*)&B[(k0 + k) * Ncols + colBase + bc0];
        }
        __syncthreads();
        #pragma unroll
        for (int k = 0; k < GBK; k++) {
            #pragma unroll
            for (int i = 0; i < GTM; i++) ra[i] = As[k][trow * GTM + i];
            #pragma unroll
            for (int j = 0; j < GTN; j++) rb[j] = Bs[k][tcol * GTN + j];
            #pragma unroll
            for (int i = 0; i < GTM; i++)
                #pragma unroll
                for (int j = 0; j < GTN; j++)
                    acc[i][j] = fmaf(ra[i], rb[j], acc[i][j]);
        }
        __syncthreads();
    }
    #pragma unroll
    for (int i = 0; i < GTM; i++) {
        int gr = rowBase + trow * GTM + i;
        if (gr < M) {
            __nv_bfloat162 p0 = __floats2bfloat162_rn(acc[i][0], acc[i][1]);
            __nv_bfloat162 p1 = __floats2bfloat162_rn(acc[i][2], acc[i][3]);
            __nv_bfloat162 p2 = __floats2bfloat162_rn(acc[i][4], acc[i][5]);
            __nv_bfloat162 p3 = __floats2bfloat162_rn(acc[i][6], acc[i][7]);
            uint4 v;
            v.x = *reinterpret_cast<unsigned int*>(&p0);
            v.y = *reinterpret_cast<unsigned int*>(&p1);
            v.z = *reinterpret_cast<unsigned int*>(&p2);
            v.w = *reinterpret_cast<unsigned int*>(&p3);
            *(uint4*)&C[gr * Ncols + colBase + tcol * GTN] = v;
        }
    }
}

// ---------------- readout ----------------
__global__ void readout_kernel(const int* __restrict__ graph_ids,
                               const float* __restrict__ Ww,
                               const float* __restrict__ bw) {
    int n = blockIdx.x * 8 + (threadIdx.x >> 5);
    int d = threadIdx.x & 31;
    if (n >= Nn) return;
    float v = 0.f;
    #pragma unroll
    for (int h = 0; h < Hh; h++) v += g_out[n * F + h * Dd + d];
    v *= (1.f / Hh);
    float wl = warpSum(v * Ww[d]);
    float w;
    if (d == 0) w = 1.f / (1.f + __expf(-(wl + bw[0])));
    w = __shfl_sync(0xffffffffu, w, 0);
    int gid = graph_ids[n];
    atomicAdd(&g_gsum[gid * Dd + d], w * v);
    atomicMaxFloat(&g_gmax[gid * Dd + d], v);
}

// ---------------- MLP head ----------------
__global__ void mlp_kernel(const float* __restrict__ Wp1, const float* __restrict__ bp1,
                           const float* __restrict__ gamma, const float* __restrict__ beta,
                           const float* __restrict__ rm, const float* __restrict__ rv,
                           const float* __restrict__ Wp2, const float* __restrict__ bp2,
                           float* __restrict__ out) {
    int g = blockIdx.x;
    int t = threadIdx.x;      // 0..127
    __shared__ float gv[2 * Dd];
    __shared__ float red[HID];
    if (t < Dd) gv[t] = g_gsum[g * Dd + t];
    else if (t < 2 * Dd) {
        float mv = g_gmax[g * Dd + (t - Dd)];
        gv[t] = isfinite(mv) ? mv : 0.f;
    }
    __syncthreads();
    float acc = bp1[t];
    #pragma unroll
    for (int k = 0; k < 2 * Dd; k++) acc = fmaf(gv[k], Wp1[k * HID + t], acc);
    acc = fmaxf(acc, 0.f);
    acc = (acc - rm[t]) * rsqrtf(rv[t] + BN_EPS) * gamma[t] + beta[t];
    red[t] = acc * Wp2[t];
    __syncthreads();
    for (int s = 64; s > 0; s >>= 1) {
        if (t < s) red[t] += red[t + s];
        __syncthreads();
    }
    if (t == 0) out[g] = red[0] + bp2[0];
}

// ---------------- launch ----------------
extern "C" void kernel_launch(void* const* d_in, const int* in_sizes, int n_in,
                              void* d_out, int out_size) {
    const float* x     = (const float*)d_in[0];
    const int*   src   = (const int*)  d_in[1];
    const int*   dst   = (const int*)  d_in[2];
    const int*   gids  = (const int*)  d_in[3];
    const float* W1    = (const float*)d_in[4];
    const float* al1   = (const float*)d_in[5];
    const float* ar1   = (const float*)d_in[6];
    const float* b1    = (const float*)d_in[7];
    const float* resW1 = (const float*)d_in[8];
    const float* W2    = (const float*)d_in[9];
    const float* al2   = (const float*)d_in[10];
    const float* ar2   = (const float*)d_in[11];
    const float* b2    = (const float*)d_in[12];
    const float* Ww    = (const float*)d_in[13];
    const float* bw    = (const float*)d_in[14];
    const float* Wp1   = (const float*)d_in[15];
    const float* bp1   = (const float*)d_in[16];
    const float* gamma = (const float*)d_in[17];
    const float* beta  = (const float*)d_in[18];
    const float* rm    = (const float*)d_in[19];
    const float* rv    = (const float*)d_in[20];
    const float* Wp2   = (const float*)d_in[21];
    const float* bp2   = (const float*)d_in[22];
    float* out = (float*)d_out;

    int* pcnt;  cudaGetSymbolAddress((void**)&pcnt, g_cnt);
    float* pgs; cudaGetSymbolAddress((void**)&pgs, g_gsum);
    float* pgm; cudaGetSymbolAddress((void**)&pgm, g_gmax);
    float* ph1; cudaGetSymbolAddress((void**)&ph1, g_h1);
    __nv_bfloat16* pfeatb; cudaGetSymbolAddress((void**)&pfeatb, g_featb);

    // one-time side stream + events (host resources, created once; no device mem)
    static cudaStream_t s2 = nullptr;
    static cudaEvent_t e1 = nullptr, e2 = nullptr;
    if (!s2) {
        cudaStreamCreateWithFlags(&s2, cudaStreamNonBlocking);
        cudaEventCreateWithFlags(&e1, cudaEventDisableTiming);
        cudaEventCreateWithFlags(&e2, cudaEventDisableTiming);
    }

    const float NEG_INF = -INFINITY;
    const int NB = (Nn + 255) / 256;   // 196 scan blocks

    // fork side stream from capture stream
    cudaEventRecord(e1, 0);
    cudaStreamWaitEvent(s2, e1, 0);

    // ===== side stream: CSR build (by dst) + readout-accumulator fills =====
    fill_int_kernel<<<NB, 256, 0, s2>>>(pcnt, Nn, 0);
    hist_kernel<<<(Ee + 255) / 256, 256, 0, s2>>>(dst);
    scan1_kernel<<<NB, 256, 0, s2>>>();
    scan2_kernel<<<1, 256, 0, s2>>>(NB);
    scan3_kernel<<<NB, 256, 0, s2>>>();
    scatter_kernel<<<(Ee + 255) / 256, 256, 0, s2>>>(src, dst);
    fill_kernel<<<(Gg * Dd + 255) / 256, 256, 0, s2>>>(pgs, Gg * Dd, 0.f);
    fill_kernel<<<(Gg * Dd + 255) / 256, 256, 0, s2>>>(pgm, Gg * Dd, NEG_INF);
    cudaEventRecord(e2, s2);

    // ===== main stream: layer 1 projection (overlaps CSR build) =====
    node1_kernel<<<(Nn + NPB - 1) / NPB, 256>>>(x, W1, resW1, b1, al1, ar1);

    // join: aggregation needs CSR
    cudaStreamWaitEvent(0, e2, 0);
    agg_kernel<true><<<Nn, 64>>>(nullptr);

    // ===== layer 2 =====
    {
        dim3 grid(F / GBN, (Nn + GBM - 1) / GBM);
        gemm_kernel<<<grid, 256>>>(ph1, W2, pfeatb, Nn);
    }
    node2el_kernel<<<Nn, 256>>>(al2, ar2);
    agg_kernel<false><<<Nn, 64>>>(b2);

    // ===== readout + MLP =====
    readout_kernel<<<(Nn + 7) / 8, 256>>>(gids, Ww, bw);
    mlp_kernel<<<Gg, HID>>>(Wp1, bp1, gamma, beta, rm, rv, Wp2, bp2, out);
}

// round 7
// speedup vs baseline: 5.5264x; 1.0221x over previous
#include <cuda_runtime.h>
#include <cuda_bf16.h>
#include <math.h>
#include <cstdint>

#define Nn 50000
#define Ee 800000
#define INF 30
#define Hh 8
#define Dd 32
#define Gg 512
#define HID 128
#define ALPHA 0.2f
#define BN_EPS 1e-5f
#define F (Hh*Dd)   // 256

typedef unsigned long long ull;

// ---------------- f32x2 packed helpers ----------------
__device__ __forceinline__ ull pack2(float lo, float hi) {
    ull p;
    asm("mov.b64 %0, {%1, %2};" : "=l"(p) : "f"(lo), "f"(hi));
    return p;
}
__device__ __forceinline__ void unpack2(ull p, float& lo, float& hi) {
    asm("mov.b64 {%0, %1}, %2;" : "=f"(lo), "=f"(hi) : "l"(p));
}
__device__ __forceinline__ ull fma2(ull a, ull b, ull c) {
    ull d;
    asm("fma.rn.f32x2 %0, %1, %2, %3;" : "=l"(d) : "l"(a), "l"(b), "l"(c));
    return d;
}

// ---------------- scratch (allocation-free: __device__ globals) ----------------
__device__ __nv_bfloat16 g_featb[Nn * F];  // projected features (bf16, gather side)
__device__ float g_base[Nn * F];     // layer1: b1 + x@resW1 (residual base)
__device__ float g_h1  [Nn * F];     // layer1 activation (fp32, GEMM A input)
__device__ float g_el  [Nn * Hh];
__device__ float g_er  [Nn * Hh];
__device__ int   g_cnt [Nn];
__device__ int   g_rowptr[Nn + 1];
__device__ int   g_cursor[Nn];
__device__ int   g_csrc[Ee];         // src node per CSR slot
__device__ int   g_bsum[256];
__device__ float g_gsum[Gg * Dd];
__device__ float g_gmax[Gg * Dd];

// ---------------- helpers ----------------
__device__ __forceinline__ void atomicMaxFloat(float* addr, float val) {
    int* ia = (int*)addr;
    int old = *ia;
    while (__int_as_float(old) < val) {
        int prev = atomicCAS(ia, old, __float_as_int(val));
        if (prev == old) break;
        old = prev;
    }
}

__device__ __forceinline__ float warpSum(float v) {
    #pragma unroll
    for (int o = 16; o > 0; o >>= 1) v += __shfl_down_sync(0xffffffffu, v, o);
    return v;
}

__global__ void fill_kernel(float* p, int n, float val) {
    int i = blockIdx.x * blockDim.x + threadIdx.x;
    if (i < n) p[i] = val;
}
__global__ void fill_int_kernel(int* p, int n, int val) {
    int i = blockIdx.x * blockDim.x + threadIdx.x;
    if (i < n) p[i] = val;
}

// ---------------- CSR build ----------------
__global__ void hist_kernel(const int* __restrict__ dst) {
    int e = blockIdx.x * blockDim.x + threadIdx.x;
    if (e < Ee) atomicAdd(&g_cnt[dst[e]], 1);
}

__global__ void scan1_kernel() {
    __shared__ int sd[256];
    int t = threadIdx.x;
    int i = blockIdx.x * 256 + t;
    int v = (i < Nn) ? g_cnt[i] : 0;
    sd[t] = v;
    __syncthreads();
    #pragma unroll
    for (int off = 1; off < 256; off <<= 1) {
        int x = (t >= off) ? sd[t - off] : 0;
        __syncthreads();
        sd[t] += x;
        __syncthreads();
    }
    if (i < Nn) g_rowptr[i] = sd[t] - v;
    if (t == 255) g_bsum[blockIdx.x] = sd[255];
}

__global__ void scan2_kernel(int nb) {
    __shared__ int sd[256];
    int t = threadIdx.x;
    int v = (t < nb) ? g_bsum[t] : 0;
    sd[t] = v;
    __syncthreads();
    #pragma unroll
    for (int off = 1; off < 256; off <<= 1) {
        int x = (t >= off) ? sd[t - off] : 0;
        __syncthreads();
        sd[t] += x;
        __syncthreads();
    }
    if (t < nb) g_bsum[t] = sd[t] - v;
    if (t == 0) g_rowptr[Nn] = Ee;
}

__global__ void scan3_kernel() {
    int i = blockIdx.x * 256 + threadIdx.x;
    if (i < Nn) {
        int r = g_rowptr[i] + g_bsum[blockIdx.x];
        g_rowptr[i] = r;
        g_cursor[i] = r;
    }
}

__global__ void scatter_kernel(const int* __restrict__ src, const int* __restrict__ dst) {
    int e = blockIdx.x * blockDim.x + threadIdx.x;
    if (e >= Ee) return;
    int d = dst[e];
    int pos = atomicAdd(&g_cursor[d], 1);
    g_csrc[pos] = src[e];
}

// ---------------- layer 1 node kernel (reg-cached W pairs, FFMA2) ----------------
#define NPB 64
__global__ void node1_kernel(const float* __restrict__ x,
                             const float* __restrict__ W1,
                             const float* __restrict__ resW1,
                             const float* __restrict__ b1,
                             const float* __restrict__ al1,
                             const float* __restrict__ ar1) {
    int j = threadIdx.x;                 // output column 0..255
    int base = blockIdx.x * NPB;
    int cnt = min(NPB, Nn - base);
    __shared__ float xs[NPB * INF];
    for (int q = j; q < cnt * INF; q += 256) xs[q] = x[base * INF + q];

    ull wp[INF];
    #pragma unroll
    for (int k = 0; k < INF; k++)
        wp[k] = pack2(W1[k * F + j], resW1[k * F + j]);
    float a_l = al1[j], a_r = ar1[j], bj = b1[j];
    __syncthreads();

    for (int u = 0; u < cnt; u++) {
        int n = base + u;
        ull acc = 0ull;    // (feat, res)
        #pragma unroll
        for (int k = 0; k < INF; k++) {
            float xv = xs[u * INF + k];
            acc = fma2(pack2(xv, xv), wp[k], acc);
        }
        float feat, res;
        unpack2(acc, feat, res);
        g_featb[n * F + j] = __float2bfloat16(feat);
        g_base [n * F + j] = bj + res;
        float elp = warpSum(feat * a_l);
        float erp = warpSum(feat * a_r);
        if ((j & 31) == 0) {
            int h = j >> 5;
            g_el[n * Hh + h] = elp;
            g_er[n * Hh + h] = erp;
        }
    }
}

// ---------------- layer 2 el/er kernel (vectorized bf16 reads, 8-lane reduce) ----------------
__global__ void node2el_kernel(const float* __restrict__ al2,
                               const float* __restrict__ ar2) {
    int n = blockIdx.x;
    int t = threadIdx.x;      // 0..63; dims [4t,4t+4), head t>>3
    uint2 u = *(const uint2*)&g_featb[n * F + t * 4];
    float2 f01 = __bfloat1622float2(*reinterpret_cast<const __nv_bfloat162*>(&u.x));
    float2 f23 = __bfloat1622float2(*reinterpret_cast<const __nv_bfloat162*>(&u.y));
    float4 al = *(const float4*)&al2[t * 4];
    float4 ar = *(const float4*)&ar2[t * 4];
    float elp = f01.x * al.x + f01.y * al.y + f23.x * al.z + f23.y * al.w;
    float erp = f01.x * ar.x + f01.y * ar.y + f23.x * ar.z + f23.y * ar.w;
    #pragma unroll
    for (int o = 4; o > 0; o >>= 1) {
        elp += __shfl_down_sync(0xffffffffu, elp, o);
        erp += __shfl_down_sync(0xffffffffu, erp, o);
    }
    if ((t & 7) == 0) {
        int h = t >> 3;
        g_el[n * Hh + h] = elp;
        g_er[n * Hh + h] = erp;
    }
}

// ---------------- layer 1: fused softmax + gather aggregation + ELU ----------------
__global__ void agg1_kernel() {
    int n = blockIdx.x;
    int t = threadIdx.x;          // 0..63
    int h = t >> 3;
    float er_h = g_er[n * Hh + h];
    int start = g_rowptr[n];
    int end   = g_rowptr[n + 1];

    float ax = 0.f, ay = 0.f, az = 0.f, aw = 0.f;
    float ssum = 0.f;
    #pragma unroll 4
    for (int e = start; e < end; e++) {
        int s = g_csrc[e];
        float v = g_el[s * Hh + h] + er_h;
        v = v > 0.f ? v : ALPHA * v;
        float ex = __expf(v);
        ssum += ex;
        uint2 u = *(const uint2*)&g_featb[s * F + t * 4];
        float2 f01 = __bfloat1622float2(*reinterpret_cast<const __nv_bfloat162*>(&u.x));
        float2 f23 = __bfloat1622float2(*reinterpret_cast<const __nv_bfloat162*>(&u.y));
        ax = fmaf(ex, f01.x, ax);
        ay = fmaf(ex, f01.y, ay);
        az = fmaf(ex, f23.x, az);
        aw = fmaf(ex, f23.y, aw);
    }
    float inv = 1.f / fmaxf(ssum, 1e-9f);

    float4 base = *(const float4*)&g_base[n * F + t * 4];   // b1 + x@resW1
    float rx = base.x + ax * inv;
    float ry = base.y + ay * inv;
    float rz = base.z + az * inv;
    float rw = base.w + aw * inv;
    rx = rx > 0.f ? rx : (__expf(rx) - 1.f);
    ry = ry > 0.f ? ry : (__expf(ry) - 1.f);
    rz = rz > 0.f ? rz : (__expf(rz) - 1.f);
    rw = rw > 0.f ? rw : (__expf(rw) - 1.f);
    *(float4*)&g_h1[n * F + t * 4] = make_float4(rx, ry, rz, rw);
}

// ---------------- layer 2: fused agg + head-mean + gated readout atomics ----------------
__global__ void agg2_kernel(const float* __restrict__ b2,
                            const int* __restrict__ graph_ids,
                            const float* __restrict__ Ww,
                            const float* __restrict__ bw) {
    int n = blockIdx.x;
    int t = threadIdx.x;          // 0..63
    int h = t >> 3;
    float er_h = g_er[n * Hh + h];
    int start = g_rowptr[n];
    int end   = g_rowptr[n + 1];

    float ax = 0.f, ay = 0.f, az = 0.f, aw = 0.f;
    float ssum = 0.f;
    #pragma unroll 4
    for (int e = start; e < end; e++) {
        int s = g_csrc[e];
        float v = g_el[s * Hh + h] + er_h;
        v = v > 0.f ? v : ALPHA * v;
        float ex = __expf(v);
        ssum += ex;
        uint2 u = *(const uint2*)&g_featb[s * F + t * 4];
        float2 f01 = __bfloat1622float2(*reinterpret_cast<const __nv_bfloat162*>(&u.x));
        float2 f23 = __bfloat1622float2(*reinterpret_cast<const __nv_bfloat162*>(&u.y));
        ax = fmaf(ex, f01.x, ax);
        ay = fmaf(ex, f01.y, ay);
        az = fmaf(ex, f23.x, az);
        aw = fmaf(ex, f23.y, aw);
    }
    float inv = 1.f / fmaxf(ssum, 1e-9f);

    float4 hb = *(const float4*)&g_h1[n * F + t * 4];
    float4 bb = *(const float4*)&b2[t * 4];
    float rx = hb.x + bb.x + ax * inv;
    float ry = hb.y + bb.y + ay * inv;
    float rz = hb.z + bb.z + az * inv;
    float rw = hb.w + bb.w + aw * inv;

    // head-mean partials: sum lanes with same (t&7) inside each warp (strides 8, 16)
    rx += __shfl_xor_sync(0xffffffffu, rx, 8);  ry += __shfl_xor_sync(0xffffffffu, ry, 8);
    rz += __shfl_xor_sync(0xffffffffu, rz, 8);  rw += __shfl_xor_sync(0xffffffffu, rw, 8);
    rx += __shfl_xor_sync(0xffffffffu, rx, 16); ry += __shfl_xor_sync(0xffffffffu, ry, 16);
    rz += __shfl_xor_sync(0xffffffffu, rz, 16); rw += __shfl_xor_sync(0xffffffffu, rw, 16);

    __shared__ float sh[2][8][4];
    int warp = t >> 5;
    if ((t & 31) < 8) {
        sh[warp][t & 7][0] = rx; sh[warp][t & 7][1] = ry;
        sh[warp][t & 7][2] = rz; sh[warp][t & 7][3] = rw;
    }
    __syncthreads();

    if (t < 32) {       // whole warp participates in shuffles; only t<8 does work
        float h0 = 0.f, h1v = 0.f, h2v = 0.f, h3 = 0.f, partial = 0.f;
        if (t < 8) {
            h0  = (sh[0][t][0] + sh[1][t][0]) * 0.125f;
            h1v = (sh[0][t][1] + sh[1][t][1]) * 0.125f;
            h2v = (sh[0][t][2] + sh[1][t][2]) * 0.125f;
            h3  = (sh[0][t][3] + sh[1][t][3]) * 0.125f;
            float4 wv = *(const float4*)&Ww[t * 4];
            partial = h0 * wv.x + h1v * wv.y + h2v * wv.z + h3 * wv.w;
        }
        #pragma unroll
        for (int o = 4; o > 0; o >>= 1) partial += __shfl_down_sync(0xffffffffu, partial, o);
        float w = 0.f;
        if (t == 0) w = 1.f / (1.f + __expf(-(partial + bw[0])));
        w = __shfl_sync(0xffffffffu, w, 0);
        if (t < 8) {
            int gid = graph_ids[n];
            float* gs = &g_gsum[gid * Dd + t * 4];
            float* gm = &g_gmax[gid * Dd + t * 4];
            atomicAdd(gs + 0, w * h0);  atomicMaxFloat(gm + 0, h0);
            atomicAdd(gs + 1, w * h1v); atomicMaxFloat(gm + 1, h1v);
            atomicAdd(gs + 2, w * h2v); atomicMaxFloat(gm + 2, h2v);
            atomicAdd(gs + 3, w * h3);  atomicMaxFloat(gm + 3, h3);
        }
    }
}

// ---------------- SGEMM (FFMA2): featb = bf16(h1 @ W2)  (M=50000, N=256, K=256) ----------------
#define GBM 128
#define GBN 128
#define GBK 16
#define GTM 8
#define GTN 8
__global__ void gemm_kernel(const float* __restrict__ A, const float* __restrict__ B,
                            __nv_bfloat16* __restrict__ C, int M) {
    const int K = F, Ncols = F;
    __shared__ float As[GBK][GBM + 4];
    __shared__ float Bs[GBK][GBN];
    int tid = threadIdx.x;                 // 256 threads
    int trow = tid >> 4;                   // 0..15
    int tcol = tid & 15;                   // 0..15
    int rowBase = blockIdx.y * GBM;
    int colBase = blockIdx.x * GBN;
    ull accp[GTM][GTN / 2] = {};           // packed fp32 pairs
    float ra[GTM];
    ull rap[GTM], rbp[GTN / 2];

    int arow = tid >> 2;                   // 0..63 (rows arow, arow+64)
    int aq = (tid & 3) * 4;                // float4 start col in BK
    int bk0 = tid >> 5;                    // 0..7
    int bc0 = (tid & 31) * 4;

    for (int k0 = 0; k0 < K; k0 += GBK) {
        #pragma unroll
        for (int half = 0; half < 2; half++) {
            int m = arow + half * 64;
            int gr = rowBase + m;
            float4 va = (gr < M) ? *(const float4*)&A[gr * K + k0 + aq]
                                 : make_float4(0.f, 0.f, 0.f, 0.f);
            As[aq + 0][m] = va.x;
            As[aq + 1][m] = va.y;
            As[aq + 2][m] = va.z;
            As[aq + 3][m] = va.w;
        }
        #pragma unroll
        for (int half = 0; half < 2; half++) {
            int k = bk0 + half * 8;
            *(float4*)&Bs[k][bc0] = *(const float4*)&B[(k0 + k) * Ncols + colBase + bc0];
        }
        __syncthreads();
        #pragma unroll
        for (int k = 0; k < GBK; k++) {
            #pragma unroll
            for (int i = 0; i < GTM; i++) {
                ra[i] = As[k][trow * GTM + i];
                rap[i] = pack2(ra[i], ra[i]);
            }
            #pragma unroll
            for (int j = 0; j < GTN / 2; j++)
                rbp[j] = *(const ull*)&Bs[k][tcol * GTN + j * 2];
            #pragma unroll
            for (int i = 0; i < GTM; i++)
                #pragma unroll
                for (int j = 0; j < GTN / 2; j++)
                    accp[i][j] = fma2(rap[i], rbp[j], accp[i][j]);
        }
        __syncthreads();
    }
    #pragma unroll
    for (int i = 0; i < GTM; i++) {
        int gr = rowBase + trow * GTM + i;
        if (gr < M) {
            float a0, a1, a2, a3, a4, a5, a6, a7;
            unpack2(accp[i][0], a0, a1);
            unpack2(accp[i][1], a2, a3);
            unpack2(accp[i][2], a4, a5);
            unpack2(accp[i][3], a6, a7);
            __nv_bfloat162 p0 = __floats2bfloat162_rn(a0, a1);
            __nv_bfloat162 p1 = __floats2bfloat162_rn(a2, a3);
            __nv_bfloat162 p2 = __floats2bfloat162_rn(a4, a5);
            __nv_bfloat162 p3 = __floats2bfloat162_rn(a6, a7);
            uint4 v;
            v.x = *reinterpret_cast<unsigned int*>(&p0);
            v.y = *reinterpret_cast<unsigned int*>(&p1);
            v.z = *reinterpret_cast<unsigned int*>(&p2);
            v.w = *reinterpret_cast<unsigned int*>(&p3);
            *(uint4*)&C[gr * Ncols + colBase + tcol * GTN] = v;
        }
    }
}

// ---------------- MLP head ----------------
__global__ void mlp_kernel(const float* __restrict__ Wp1, const float* __restrict__ bp1,
                           const float* __restrict__ gamma, const float* __restrict__ beta,
                           const float* __restrict__ rm, const float* __restrict__ rv,
                           const float* __restrict__ Wp2, const float* __restrict__ bp2,
                           float* __restrict__ out) {
    int g = blockIdx.x;
    int t = threadIdx.x;      // 0..127
    __shared__ float gv[2 * Dd];
    __shared__ float red[HID];
    if (t < Dd) gv[t] = g_gsum[g * Dd + t];
    else if (t < 2 * Dd) {
        float mv = g_gmax[g * Dd + (t - Dd)];
        gv[t] = isfinite(mv) ? mv : 0.f;
    }
    __syncthreads();
    float acc = bp1[t];
    #pragma unroll
    for (int k = 0; k < 2 * Dd; k++) acc = fmaf(gv[k], Wp1[k * HID + t], acc);
    acc = fmaxf(acc, 0.f);
    acc = (acc - rm[t]) * rsqrtf(rv[t] + BN_EPS) * gamma[t] + beta[t];
    red[t] = acc * Wp2[t];
    __syncthreads();
    for (int s = 64; s > 0; s >>= 1) {
        if (t < s) red[t] += red[t + s];
        __syncthreads();
    }
    if (t == 0) out[g] = red[0] + bp2[0];
}

// ---------------- launch ----------------
extern "C" void kernel_launch(void* const* d_in, const int* in_sizes, int n_in,
                              void* d_out, int out_size) {
    const float* x     = (const float*)d_in[0];
    const int*   src   = (const int*)  d_in[1];
    const int*   dst   = (const int*)  d_in[2];
    const int*   gids  = (const int*)  d_in[3];
    const float* W1    = (const float*)d_in[4];
    const float* al1   = (const float*)d_in[5];
    const float* ar1   = (const float*)d_in[6];
    const float* b1    = (const float*)d_in[7];
    const float* resW1 = (const float*)d_in[8];
    const float* W2    = (const float*)d_in[9];
    const float* al2   = (const float*)d_in[10];
    const float* ar2   = (const float*)d_in[11];
    const float* b2    = (const float*)d_in[12];
    const float* Ww    = (const float*)d_in[13];
    const float* bw    = (const float*)d_in[14];
    const float* Wp1   = (const float*)d_in[15];
    const float* bp1   = (const float*)d_in[16];
    const float* gamma = (const float*)d_in[17];
    const float* beta  = (const float*)d_in[18];
    const float* rm    = (const float*)d_in[19];
    const float* rv    = (const float*)d_in[20];
    const float* Wp2   = (const float*)d_in[21];
    const float* bp2   = (const float*)d_in[22];
    float* out = (float*)d_out;

    int* pcnt;  cudaGetSymbolAddress((void**)&pcnt, g_cnt);
    float* pgs; cudaGetSymbolAddress((void**)&pgs, g_gsum);
    float* pgm; cudaGetSymbolAddress((void**)&pgm, g_gmax);
    float* ph1; cudaGetSymbolAddress((void**)&ph1, g_h1);
    __nv_bfloat16* pfeatb; cudaGetSymbolAddress((void**)&pfeatb, g_featb);

    static cudaStream_t s2 = nullptr;
    static cudaEvent_t e1 = nullptr, e2 = nullptr;
    if (!s2) {
        cudaStreamCreateWithFlags(&s2, cudaStreamNonBlocking);
        cudaEventCreateWithFlags(&e1, cudaEventDisableTiming);
        cudaEventCreateWithFlags(&e2, cudaEventDisableTiming);
    }

    const float NEG_INF = -INFINITY;
    const int NB = (Nn + 255) / 256;

    cudaEventRecord(e1, 0);
    cudaStreamWaitEvent(s2, e1, 0);

    // ===== side stream: CSR build + readout-accumulator fills =====
    fill_int_kernel<<<NB, 256, 0, s2>>>(pcnt, Nn, 0);
    hist_kernel<<<(Ee + 255) / 256, 256, 0, s2>>>(dst);
    scan1_kernel<<<NB, 256, 0, s2>>>();
    scan2_kernel<<<1, 256, 0, s2>>>(NB);
    scan3_kernel<<<NB, 256, 0, s2>>>();
    scatter_kernel<<<(Ee + 255) / 256, 256, 0, s2>>>(src, dst);
    fill_kernel<<<(Gg * Dd + 255) / 256, 256, 0, s2>>>(pgs, Gg * Dd, 0.f);
    fill_kernel<<<(Gg * Dd + 255) / 256, 256, 0, s2>>>(pgm, Gg * Dd, NEG_INF);
    cudaEventRecord(e2, s2);

    // ===== main stream: layer 1 projection (overlaps CSR build) =====
    node1_kernel<<<(Nn + NPB - 1) / NPB, 256>>>(x, W1, resW1, b1, al1, ar1);

    cudaStreamWaitEvent(0, e2, 0);
    agg1_kernel<<<Nn, 64>>>();

    // ===== layer 2 =====
    {
        dim3 grid(F / GBN, (Nn + GBM - 1) / GBM);
        gemm_kernel<<<grid, 256>>>(ph1, W2, pfeatb, Nn);
    }
    node2el_kernel<<<Nn, 64>>>(al2, ar2);
    agg2_kernel<<<Nn, 64>>>(b2, gids, Ww, bw);

    // ===== MLP =====
    mlp_kernel<<<Gg, HID>>>(Wp1, bp1, gamma, beta, rm, rv, Wp2, bp2, out);
}

// round 8
// speedup vs baseline: 6.9763x; 1.2624x over previous
#include <cuda_runtime.h>
#include <cuda_bf16.h>
#include <math.h>
#include <cstdint>

#define Nn 50000
#define Ee 800000
#define INF 30
#define Hh 8
#define Dd 32
#define Gg 512
#define HID 128
#define ALPHA 0.2f
#define BN_EPS 1e-5f
#define F (Hh*Dd)   // 256

typedef unsigned long long ull;

// ---------------- f32x2 packed helpers ----------------
__device__ __forceinline__ ull pack2(float lo, float hi) {
    ull p;
    asm("mov.b64 %0, {%1, %2};" : "=l"(p) : "f"(lo), "f"(hi));
    return p;
}
__device__ __forceinline__ void unpack2(ull p, float& lo, float& hi) {
    asm("mov.b64 {%0, %1}, %2;" : "=f"(lo), "=f"(hi) : "l"(p));
}
__device__ __forceinline__ ull fma2(ull a, ull b, ull c) {
    ull d;
    asm("fma.rn.f32x2 %0, %1, %2, %3;" : "=l"(d) : "l"(a), "l"(b), "l"(c));
    return d;
}
__device__ __forceinline__ unsigned f2tf32(float f) {
    unsigned u;
    asm("cvt.rna.tf32.f32 %0, %1;" : "=r"(u) : "f"(f));
    return u;
}

// ---------------- scratch (allocation-free: __device__ globals) ----------------
__device__ __nv_bfloat16 g_featb[Nn * F];  // projected features (bf16, gather side)
__device__ float g_base[Nn * F];     // layer1: b1 + x@resW1 (residual base)
__device__ float g_h1  [Nn * F];     // layer1 activation (fp32, GEMM A input)
__device__ float g_el  [Nn * Hh];
__device__ float g_er  [Nn * Hh];
__device__ int   g_cnt [Nn];
__device__ int   g_rowptr[Nn + 1];
__device__ int   g_cursor[Nn];
__device__ int   g_csrc[Ee];         // src node per CSR slot
__device__ int   g_bsum[256];
__device__ float g_gsum[Gg * Dd];
__device__ float g_gmax[Gg * Dd];

// ---------------- helpers ----------------
__device__ __forceinline__ void atomicMaxFloat(float* addr, float val) {
    int* ia = (int*)addr;
    int old = *ia;
    while (__int_as_float(old) < val) {
        int prev = atomicCAS(ia, old, __float_as_int(val));
        if (prev == old) break;
        old = prev;
    }
}

__device__ __forceinline__ float warpSum(float v) {
    #pragma unroll
    for (int o = 16; o > 0; o >>= 1) v += __shfl_down_sync(0xffffffffu, v, o);
    return v;
}

__global__ void fill_kernel(float* p, int n, float val) {
    int i = blockIdx.x * blockDim.x + threadIdx.x;
    if (i < n) p[i] = val;
}
__global__ void fill_int_kernel(int* p, int n, int val) {
    int i = blockIdx.x * blockDim.x + threadIdx.x;
    if (i < n) p[i] = val;
}

// ---------------- CSR build ----------------
__global__ void hist_kernel(const int* __restrict__ dst) {
    int e = blockIdx.x * blockDim.x + threadIdx.x;
    if (e < Ee) atomicAdd(&g_cnt[dst[e]], 1);
}

__global__ void scan1_kernel() {
    __shared__ int sd[256];
    int t = threadIdx.x;
    int i = blockIdx.x * 256 + t;
    int v = (i < Nn) ? g_cnt[i] : 0;
    sd[t] = v;
    __syncthreads();
    #pragma unroll
    for (int off = 1; off < 256; off <<= 1) {
        int x = (t >= off) ? sd[t - off] : 0;
        __syncthreads();
        sd[t] += x;
        __syncthreads();
    }
    if (i < Nn) g_rowptr[i] = sd[t] - v;
    if (t == 255) g_bsum[blockIdx.x] = sd[255];
}

__global__ void scan2_kernel(int nb) {
    __shared__ int sd[256];
    int t = threadIdx.x;
    int v = (t < nb) ? g_bsum[t] : 0;
    sd[t] = v;
    __syncthreads();
    #pragma unroll
    for (int off = 1; off < 256; off <<= 1) {
        int x = (t >= off) ? sd[t - off] : 0;
        __syncthreads();
        sd[t] += x;
        __syncthreads();
    }
    if (t < nb) g_bsum[t] = sd[t] - v;
    if (t == 0) g_rowptr[Nn] = Ee;
}

__global__ void scan3_kernel() {
    int i = blockIdx.x * 256 + threadIdx.x;
    if (i < Nn) {
        int r = g_rowptr[i] + g_bsum[blockIdx.x];
        g_rowptr[i] = r;
        g_cursor[i] = r;
    }
}

__global__ void scatter_kernel(const int* __restrict__ src, const int* __restrict__ dst) {
    int e = blockIdx.x * blockDim.x + threadIdx.x;
    if (e >= Ee) return;
    int d = dst[e];
    int pos = atomicAdd(&g_cursor[d], 1);
    g_csrc[pos] = src[e];
}

// ---------------- layer 1 node kernel (reg-cached W pairs, FFMA2) ----------------
#define NPB 64
__global__ void node1_kernel(const float* __restrict__ x,
                             const float* __restrict__ W1,
                             const float* __restrict__ resW1,
                             const float* __restrict__ b1,
                             const float* __restrict__ al1,
                             const float* __restrict__ ar1) {
    int j = threadIdx.x;                 // output column 0..255
    int base = blockIdx.x * NPB;
    int cnt = min(NPB, Nn - base);
    __shared__ float xs[NPB * INF];
    for (int q = j; q < cnt * INF; q += 256) xs[q] = x[base * INF + q];

    ull wp[INF];
    #pragma unroll
    for (int k = 0; k < INF; k++)
        wp[k] = pack2(W1[k * F + j], resW1[k * F + j]);
    float a_l = al1[j], a_r = ar1[j], bj = b1[j];
    __syncthreads();

    for (int u = 0; u < cnt; u++) {
        int n = base + u;
        ull acc = 0ull;    // (feat, res)
        #pragma unroll
        for (int k = 0; k < INF; k++) {
            float xv = xs[u * INF + k];
            acc = fma2(pack2(xv, xv), wp[k], acc);
        }
        float feat, res;
        unpack2(acc, feat, res);
        g_featb[n * F + j] = __float2bfloat16(feat);
        g_base [n * F + j] = bj + res;
        float elp = warpSum(feat * a_l);
        float erp = warpSum(feat * a_r);
        if ((j & 31) == 0) {
            int h = j >> 5;
            g_el[n * Hh + h] = elp;
            g_er[n * Hh + h] = erp;
        }
    }
}

// ---------------- layer 2 el/er kernel (vectorized bf16 reads, 8-lane reduce) ----------------
__global__ void node2el_kernel(const float* __restrict__ al2,
                               const float* __restrict__ ar2) {
    int n = blockIdx.x;
    int t = threadIdx.x;      // 0..63; dims [4t,4t+4), head t>>3
    uint2 u = *(const uint2*)&g_featb[n * F + t * 4];
    float2 f01 = __bfloat1622float2(*reinterpret_cast<const __nv_bfloat162*>(&u.x));
    float2 f23 = __bfloat1622float2(*reinterpret_cast<const __nv_bfloat162*>(&u.y));
    float4 al = *(const float4*)&al2[t * 4];
    float4 ar = *(const float4*)&ar2[t * 4];
    float elp = f01.x * al.x + f01.y * al.y + f23.x * al.z + f23.y * al.w;
    float erp = f01.x * ar.x + f01.y * ar.y + f23.x * ar.z + f23.y * ar.w;
    #pragma unroll
    for (int o = 4; o > 0; o >>= 1) {
        elp += __shfl_down_sync(0xffffffffu, elp, o);
        erp += __shfl_down_sync(0xffffffffu, erp, o);
    }
    if ((t & 7) == 0) {
        int h = t >> 3;
        g_el[n * Hh + h] = elp;
        g_er[n * Hh + h] = erp;
    }
}

// ---------------- layer 1: fused softmax + gather aggregation + ELU ----------------
__global__ void agg1_kernel() {
    int n = blockIdx.x;
    int t = threadIdx.x;          // 0..63
    int h = t >> 3;
    float er_h = g_er[n * Hh + h];
    int start = g_rowptr[n];
    int end   = g_rowptr[n + 1];

    float ax = 0.f, ay = 0.f, az = 0.f, aw = 0.f;
    float ssum = 0.f;
    #pragma unroll 4
    for (int e = start; e < end; e++) {
        int s = g_csrc[e];
        float v = g_el[s * Hh + h] + er_h;
        v = v > 0.f ? v : ALPHA * v;
        float ex = __expf(v);
        ssum += ex;
        uint2 u = *(const uint2*)&g_featb[s * F + t * 4];
        float2 f01 = __bfloat1622float2(*reinterpret_cast<const __nv_bfloat162*>(&u.x));
        float2 f23 = __bfloat1622float2(*reinterpret_cast<const __nv_bfloat162*>(&u.y));
        ax = fmaf(ex, f01.x, ax);
        ay = fmaf(ex, f01.y, ay);
        az = fmaf(ex, f23.x, az);
        aw = fmaf(ex, f23.y, aw);
    }
    float inv = 1.f / fmaxf(ssum, 1e-9f);

    float4 base = *(const float4*)&g_base[n * F + t * 4];   // b1 + x@resW1
    float rx = base.x + ax * inv;
    float ry = base.y + ay * inv;
    float rz = base.z + az * inv;
    float rw = base.w + aw * inv;
    rx = rx > 0.f ? rx : (__expf(rx) - 1.f);
    ry = ry > 0.f ? ry : (__expf(ry) - 1.f);
    rz = rz > 0.f ? rz : (__expf(rz) - 1.f);
    rw = rw > 0.f ? rw : (__expf(rw) - 1.f);
    *(float4*)&g_h1[n * F + t * 4] = make_float4(rx, ry, rz, rw);
}

// ---------------- layer 2: fused agg + head-mean + gated readout atomics ----------------
__global__ void agg2_kernel(const float* __restrict__ b2,
                            const int* __restrict__ graph_ids,
                            const float* __restrict__ Ww,
                            const float* __restrict__ bw) {
    int n = blockIdx.x;
    int t = threadIdx.x;          // 0..63
    int h = t >> 3;
    float er_h = g_er[n * Hh + h];
    int start = g_rowptr[n];
    int end   = g_rowptr[n + 1];

    float ax = 0.f, ay = 0.f, az = 0.f, aw = 0.f;
    float ssum = 0.f;
    #pragma unroll 4
    for (int e = start; e < end; e++) {
        int s = g_csrc[e];
        float v = g_el[s * Hh + h] + er_h;
        v = v > 0.f ? v : ALPHA * v;
        float ex = __expf(v);
        ssum += ex;
        uint2 u = *(const uint2*)&g_featb[s * F + t * 4];
        float2 f01 = __bfloat1622float2(*reinterpret_cast<const __nv_bfloat162*>(&u.x));
        float2 f23 = __bfloat1622float2(*reinterpret_cast<const __nv_bfloat162*>(&u.y));
        ax = fmaf(ex, f01.x, ax);
        ay = fmaf(ex, f01.y, ay);
        az = fmaf(ex, f23.x, az);
        aw = fmaf(ex, f23.y, aw);
    }
    float inv = 1.f / fmaxf(ssum, 1e-9f);

    float4 hb = *(const float4*)&g_h1[n * F + t * 4];
    float4 bb = *(const float4*)&b2[t * 4];
    float rx = hb.x + bb.x + ax * inv;
    float ry = hb.y + bb.y + ay * inv;
    float rz = hb.z + bb.z + az * inv;
    float rw = hb.w + bb.w + aw * inv;

    // head-mean partials: sum lanes with same (t&7) inside each warp (strides 8, 16)
    rx += __shfl_xor_sync(0xffffffffu, rx, 8);  ry += __shfl_xor_sync(0xffffffffu, ry, 8);
    rz += __shfl_xor_sync(0xffffffffu, rz, 8);  rw += __shfl_xor_sync(0xffffffffu, rw, 8);
    rx += __shfl_xor_sync(0xffffffffu, rx, 16); ry += __shfl_xor_sync(0xffffffffu, ry, 16);
    rz += __shfl_xor_sync(0xffffffffu, rz, 16); rw += __shfl_xor_sync(0xffffffffu, rw, 16);

    __shared__ float sh[2][8][4];
    int warp = t >> 5;
    if ((t & 31) < 8) {
        sh[warp][t & 7][0] = rx; sh[warp][t & 7][1] = ry;
        sh[warp][t & 7][2] = rz; sh[warp][t & 7][3] = rw;
    }
    __syncthreads();

    if (t < 32) {
        float h0 = 0.f, h1v = 0.f, h2v = 0.f, h3 = 0.f, partial = 0.f;
        if (t < 8) {
            h0  = (sh[0][t][0] + sh[1][t][0]) * 0.125f;
            h1v = (sh[0][t][1] + sh[1][t][1]) * 0.125f;
            h2v = (sh[0][t][2] + sh[1][t][2]) * 0.125f;
            h3  = (sh[0][t][3] + sh[1][t][3]) * 0.125f;
            float4 wv = *(const float4*)&Ww[t * 4];
            partial = h0 * wv.x + h1v * wv.y + h2v * wv.z + h3 * wv.w;
        }
        #pragma unroll
        for (int o = 4; o > 0; o >>= 1) partial += __shfl_down_sync(0xffffffffu, partial, o);
        float w = 0.f;
        if (t == 0) w = 1.f / (1.f + __expf(-(partial + bw[0])));
        w = __shfl_sync(0xffffffffu, w, 0);
        if (t < 8) {
            int gid = graph_ids[n];
            float* gs = &g_gsum[gid * Dd + t * 4];
            float* gm = &g_gmax[gid * Dd + t * 4];
            atomicAdd(gs + 0, w * h0);  atomicMaxFloat(gm + 0, h0);
            atomicAdd(gs + 1, w * h1v); atomicMaxFloat(gm + 1, h1v);
            atomicAdd(gs + 2, w * h2v); atomicMaxFloat(gm + 2, h2v);
            atomicAdd(gs + 3, w * h3);  atomicMaxFloat(gm + 3, h3);
        }
    }
}

// ---------------- tf32 tensor-core GEMM: featb = bf16(h1 @ W2) (M=50000,N=256,K=256) ----------------
#define TBM 128
#define TBN 128
#define TBK 32
__global__ void gemm_tc_kernel(const float* __restrict__ A, const float* __restrict__ B,
                               __nv_bfloat16* __restrict__ C, int M) {
    __shared__ float As[TBM][TBK + 4];   // [m][k], row stride 36 floats
    __shared__ float Bs[TBK][TBN + 4];   // [k][n], row stride 132 floats
    int tid = threadIdx.x;
    int lane = tid & 31, warp = tid >> 5;
    int g = lane >> 2, tig = lane & 3;
    int mw = (warp & 1) * 64;            // warp tile 64x32
    int nw = (warp >> 1) * 32;
    int rowBase = blockIdx.y * TBM;
    int colBase = blockIdx.x * TBN;

    float c[4][4][4];
    #pragma unroll
    for (int mt = 0; mt < 4; mt++)
        #pragma unroll
        for (int nt = 0; nt < 4; nt++)
            #pragma unroll
            for (int q = 0; q < 4; q++) c[mt][nt][q] = 0.f;

    for (int k0 = 0; k0 < F; k0 += TBK) {
        // A tile: 128x32 floats, tf32-converted on the way in
        #pragma unroll
        for (int i = 0; i < 4; i++) {
            int id = tid + i * 256;
            int r = id >> 3, c4 = (id & 7) * 4;
            int gr = rowBase + r;
            float4 v = (gr < M) ? *(const float4*)&A[gr * F + k0 + c4]
                                : make_float4(0.f, 0.f, 0.f, 0.f);
            uint4 u;
            u.x = f2tf32(v.x); u.y = f2tf32(v.y); u.z = f2tf32(v.z); u.w = f2tf32(v.w);
            *(uint4*)&As[r][c4] = u;
        }
        // B tile: 32x128 floats
        #pragma unroll
        for (int i = 0; i < 4; i++) {
            int id = tid + i * 256;
            int r = id >> 5, c4 = (id & 31) * 4;
            float4 v = *(const float4*)&B[(k0 + r) * F + colBase + c4];
            uint4 u;
            u.x = f2tf32(v.x); u.y = f2tf32(v.y); u.z = f2tf32(v.z); u.w = f2tf32(v.w);
            *(uint4*)&Bs[r][c4] = u;
        }
        __syncthreads();
        #pragma unroll
        for (int k8 = 0; k8 < TBK; k8 += 8) {
            unsigned a[4][4], b[4][2];
            #pragma unroll
            for (int mt = 0; mt < 4; mt++) {
                int r0 = mw + mt * 16;
                a[mt][0] = __float_as_uint(As[r0 + g][k8 + tig]);
                a[mt][1] = __float_as_uint(As[r0 + g + 8][k8 + tig]);
                a[mt][2] = __float_as_uint(As[r0 + g][k8 + tig + 4]);
                a[mt][3] = __float_as_uint(As[r0 + g + 8][k8 + tig + 4]);
            }
            #pragma unroll
            for (int nt = 0; nt < 4; nt++) {
                int cn = nw + nt * 8;
                b[nt][0] = __float_as_uint(Bs[k8 + tig][cn + g]);
                b[nt][1] = __float_as_uint(Bs[k8 + tig + 4][cn + g]);
            }
            #pragma unroll
            for (int mt = 0; mt < 4; mt++)
                #pragma unroll
                for (int nt = 0; nt < 4; nt++)
                    asm volatile(
                        "mma.sync.aligned.m16n8k8.row.col.f32.tf32.tf32.f32 "
                        "{%0,%1,%2,%3},{%4,%5,%6,%7},{%8,%9},{%0,%1,%2,%3};"
                        : "+f"(c[mt][nt][0]), "+f"(c[mt][nt][1]),
                          "+f"(c[mt][nt][2]), "+f"(c[mt][nt][3])
                        : "r"(a[mt][0]), "r"(a[mt][1]), "r"(a[mt][2]), "r"(a[mt][3]),
                          "r"(b[nt][0]), "r"(b[nt][1]));
        }
        __syncthreads();
    }

    // epilogue: bf16 stores. c0/c1 -> (row g, col tig*2, +1); c2/c3 -> row g+8.
    #pragma unroll
    for (int mt = 0; mt < 4; mt++) {
        int gr0 = rowBase + mw + mt * 16 + g;
        int gr1 = gr0 + 8;
        #pragma unroll
        for (int nt = 0; nt < 4; nt++) {
            int col = colBase + nw + nt * 8 + tig * 2;
            if (gr0 < M) {
                __nv_bfloat162 p = __floats2bfloat162_rn(c[mt][nt][0], c[mt][nt][1]);
                *(__nv_bfloat162*)&C[gr0 * F + col] = p;
            }
            if (gr1 < M) {
                __nv_bfloat162 p = __floats2bfloat162_rn(c[mt][nt][2], c[mt][nt][3]);
                *(__nv_bfloat162*)&C[gr1 * F + col] = p;
            }
        }
    }
}

// ---------------- MLP head ----------------
__global__ void mlp_kernel(const float* __restrict__ Wp1, const float* __restrict__ bp1,
                           const float* __restrict__ gamma, const float* __restrict__ beta,
                           const float* __restrict__ rm, const float* __restrict__ rv,
                           const float* __restrict__ Wp2, const float* __restrict__ bp2,
                           float* __restrict__ out) {
    int g = blockIdx.x;
    int t = threadIdx.x;      // 0..127
    __shared__ float gv[2 * Dd];
    __shared__ float red[HID];
    if (t < Dd) gv[t] = g_gsum[g * Dd + t];
    else if (t < 2 * Dd) {
        float mv = g_gmax[g * Dd + (t - Dd)];
        gv[t] = isfinite(mv) ? mv : 0.f;
    }
    __syncthreads();
    float acc = bp1[t];
    #pragma unroll
    for (int k = 0; k < 2 * Dd; k++) acc = fmaf(gv[k], Wp1[k * HID + t], acc);
    acc = fmaxf(acc, 0.f);
    acc = (acc - rm[t]) * rsqrtf(rv[t] + BN_EPS) * gamma[t] + beta[t];
    red[t] = acc * Wp2[t];
    __syncthreads();
    for (int s = 64; s > 0; s >>= 1) {
        if (t < s) red[t] += red[t + s];
        __syncthreads();
    }
    if (t == 0) out[g] = red[0] + bp2[0];
}

// ---------------- launch ----------------
extern "C" void kernel_launch(void* const* d_in, const int* in_sizes, int n_in,
                              void* d_out, int out_size) {
    const float* x     = (const float*)d_in[0];
    const int*   src   = (const int*)  d_in[1];
    const int*   dst   = (const int*)  d_in[2];
    const int*   gids  = (const int*)  d_in[3];
    const float* W1    = (const float*)d_in[4];
    const float* al1   = (const float*)d_in[5];
    const float* ar1   = (const float*)d_in[6];
    const float* b1    = (const float*)d_in[7];
    const float* resW1 = (const float*)d_in[8];
    const float* W2    = (const float*)d_in[9];
    const float* al2   = (const float*)d_in[10];
    const float* ar2   = (const float*)d_in[11];
    const float* b2    = (const float*)d_in[12];
    const float* Ww    = (const float*)d_in[13];
    const float* bw    = (const float*)d_in[14];
    const float* Wp1   = (const float*)d_in[15];
    const float* bp1   = (const float*)d_in[16];
    const float* gamma = (const float*)d_in[17];
    const float* beta  = (const float*)d_in[18];
    const float* rm    = (const float*)d_in[19];
    const float* rv    = (const float*)d_in[20];
    const float* Wp2   = (const float*)d_in[21];
    const float* bp2   = (const float*)d_in[22];
    float* out = (float*)d_out;

    int* pcnt;  cudaGetSymbolAddress((void**)&pcnt, g_cnt);
    float* pgs; cudaGetSymbolAddress((void**)&pgs, g_gsum);
    float* pgm; cudaGetSymbolAddress((void**)&pgm, g_gmax);
    float* ph1; cudaGetSymbolAddress((void**)&ph1, g_h1);
    __nv_bfloat16* pfeatb; cudaGetSymbolAddress((void**)&pfeatb, g_featb);

    static cudaStream_t s2 = nullptr;
    static cudaEvent_t e1 = nullptr, e2 = nullptr;
    if (!s2) {
        cudaStreamCreateWithFlags(&s2, cudaStreamNonBlocking);
        cudaEventCreateWithFlags(&e1, cudaEventDisableTiming);
        cudaEventCreateWithFlags(&e2, cudaEventDisableTiming);
    }

    const float NEG_INF = -INFINITY;
    const int NB = (Nn + 255) / 256;

    cudaEventRecord(e1, 0);
    cudaStreamWaitEvent(s2, e1, 0);

    // ===== side stream: CSR build + readout-accumulator fills =====
    fill_int_kernel<<<NB, 256, 0, s2>>>(pcnt, Nn, 0);
    hist_kernel<<<(Ee + 255) / 256, 256, 0, s2>>>(dst);
    scan1_kernel<<<NB, 256, 0, s2>>>();
    scan2_kernel<<<1, 256, 0, s2>>>(NB);
    scan3_kernel<<<NB, 256, 0, s2>>>();
    scatter_kernel<<<(Ee + 255) / 256, 256, 0, s2>>>(src, dst);
    fill_kernel<<<(Gg * Dd + 255) / 256, 256, 0, s2>>>(pgs, Gg * Dd, 0.f);
    fill_kernel<<<(Gg * Dd + 255) / 256, 256, 0, s2>>>(pgm, Gg * Dd, NEG_INF);
    cudaEventRecord(e2, s2);

    // ===== main stream: layer 1 projection (overlaps CSR build) =====
    node1_kernel<<<(Nn + NPB - 1) / NPB, 256>>>(x, W1, resW1, b1, al1, ar1);

    cudaStreamWaitEvent(0, e2, 0);
    agg1_kernel<<<Nn, 64>>>();

    // ===== layer 2 =====
    {
        dim3 grid(F / TBN, (Nn + TBM - 1) / TBM);
        gemm_tc_kernel<<<grid, 256>>>(ph1, W2, pfeatb, Nn);
    }
    node2el_kernel<<<Nn, 64>>>(al2, ar2);
    agg2_kernel<<<Nn, 64>>>(b2, gids, Ww, bw);

    // ===== MLP =====
    mlp_kernel<<<Gg, HID>>>(Wp1, bp1, gamma, beta, rm, rv, Wp2, bp2, out);
}

// round 9
// speedup vs baseline: 8.0148x; 1.1489x over previous
#include <cuda_runtime.h>
#include <cuda_bf16.h>
#include <math.h>
#include <cstdint>

#define Nn 50000
#define Ee 800000
#define INF 30
#define Hh 8
#define Dd 32
#define Gg 512
#define HID 128
#define ALPHA 0.2f
#define BN_EPS 1e-5f
#define F (Hh*Dd)   // 256

// ---------------- helpers ----------------
__device__ __forceinline__ unsigned f2tf32(float f) {
    unsigned u;
    asm("cvt.rna.tf32.f32 %0, %1;" : "=r"(u) : "f"(f));
    return u;
}

__device__ __forceinline__ void atomicMaxFloat(float* addr, float val) {
    int* ia = (int*)addr;
    int old = *ia;
    while (__int_as_float(old) < val) {
        int prev = atomicCAS(ia, old, __float_as_int(val));
        if (prev == old) break;
        old = prev;
    }
}

// ---------------- scratch (allocation-free: __device__ globals) ----------------
__device__ __nv_bfloat16 g_featb[Nn * F];  // projected features (bf16, gather side)
__device__ float g_base[Nn * F];     // layer1: b1 + x@resW1 (residual base)
__device__ float g_h1  [Nn * F];     // layer1 activation (fp32, GEMM A input)
__device__ float g_el  [Nn * Hh];
__device__ float g_er  [Nn * Hh];
__device__ int   g_cnt [Nn];
__device__ int   g_rowptr[Nn + 1];
__device__ int   g_cursor[Nn];
__device__ int   g_csrc[Ee];         // src node per CSR slot
__device__ int   g_bsum[256];
__device__ float g_gsum[Gg * Dd];
__device__ float g_gmax[Gg * Dd];

__global__ void fill_kernel(float* p, int n, float val) {
    int i = blockIdx.x * blockDim.x + threadIdx.x;
    if (i < n) p[i] = val;
}
__global__ void fill_int_kernel(int* p, int n, int val) {
    int i = blockIdx.x * blockDim.x + threadIdx.x;
    if (i < n) p[i] = val;
}

// ---------------- CSR build ----------------
__global__ void hist_kernel(const int* __restrict__ dst) {
    int e = blockIdx.x * blockDim.x + threadIdx.x;
    if (e < Ee) atomicAdd(&g_cnt[dst[e]], 1);
}

__global__ void scan1_kernel() {
    __shared__ int sd[256];
    int t = threadIdx.x;
    int i = blockIdx.x * 256 + t;
    int v = (i < Nn) ? g_cnt[i] : 0;
    sd[t] = v;
    __syncthreads();
    #pragma unroll
    for (int off = 1; off < 256; off <<= 1) {
        int x = (t >= off) ? sd[t - off] : 0;
        __syncthreads();
        sd[t] += x;
        __syncthreads();
    }
    if (i < Nn) g_rowptr[i] = sd[t] - v;
    if (t == 255) g_bsum[blockIdx.x] = sd[255];
}

__global__ void scan2_kernel(int nb) {
    __shared__ int sd[256];
    int t = threadIdx.x;
    int v = (t < nb) ? g_bsum[t] : 0;
    sd[t] = v;
    __syncthreads();
    #pragma unroll
    for (int off = 1; off < 256; off <<= 1) {
        int x = (t >= off) ? sd[t - off] : 0;
        __syncthreads();
        sd[t] += x;
        __syncthreads();
    }
    if (t < nb) g_bsum[t] = sd[t] - v;
    if (t == 0) g_rowptr[Nn] = Ee;
}

__global__ void scan3_kernel() {
    int i = blockIdx.x * 256 + threadIdx.x;
    if (i < Nn) {
        int r = g_rowptr[i] + g_bsum[blockIdx.x];
        g_rowptr[i] = r;
        g_cursor[i] = r;
    }
}

__global__ void scatter_kernel(const int* __restrict__ src, const int* __restrict__ dst) {
    int e = blockIdx.x * blockDim.x + threadIdx.x;
    if (e >= Ee) return;
    int d = dst[e];
    int pos = atomicAdd(&g_cursor[d], 1);
    g_csrc[pos] = src[e];
}

// ================= layer-1 tensor-core projection =================
// C[50000, 512] = x[50000,30] @ [W1 | resW1], K padded to 32.
// Blocks with colBase<256: write featb (bf16) + el1/er1 from accumulators.
// Blocks with colBase>=256: write g_base = b1 + x@resW1 (fp32).
__global__ void node1_tc_kernel(const float* __restrict__ x,
                                const float* __restrict__ W1,
                                const float* __restrict__ resW1,
                                const float* __restrict__ b1,
                                const float* __restrict__ al1,
                                const float* __restrict__ ar1) {
    __shared__ float As[128][36];
    __shared__ float Bs[32][132];
    int tid = threadIdx.x;
    int lane = tid & 31, warp = tid >> 5;
    int g = lane >> 2, tig = lane & 3;
    int mw = (warp & 1) * 64;
    int nw = (warp >> 1) * 32;
    int rowBase = blockIdx.y * 128;
    int colBase = blockIdx.x * 128;     // 0,128 = feat; 256,384 = residual

    // A tile: 128x32, tf32 converted (cols >= 30 zero)
    #pragma unroll
    for (int i = 0; i < 16; i++) {
        int id = tid + i * 256;
        int r = id >> 5, c = id & 31;
        int gr = rowBase + r;
        float v = (gr < Nn && c < INF) ? x[gr * INF + c] : 0.f;
        As[r][c] = __uint_as_float(f2tf32(v));
    }
    // B tile: 32x128 from W1/resW1 (rows >= 30 zero)
    #pragma unroll
    for (int i = 0; i < 16; i++) {
        int id = tid + i * 256;
        int r = id >> 7, c = id & 127;
        int j = colBase + c;
        float v = 0.f;
        if (r < INF) v = (j < 256) ? W1[r * 256 + j] : resW1[r * 256 + (j - 256)];
        Bs[r][c] = __uint_as_float(f2tf32(v));
    }
    __syncthreads();

    float cf[4][4][4];
    #pragma unroll
    for (int mt = 0; mt < 4; mt++)
        #pragma unroll
        for (int nt = 0; nt < 4; nt++)
            #pragma unroll
            for (int q = 0; q < 4; q++) cf[mt][nt][q] = 0.f;

    #pragma unroll
    for (int k8 = 0; k8 < 32; k8 += 8) {
        unsigned a[4][4], b[4][2];
        #pragma unroll
        for (int mt = 0; mt < 4; mt++) {
            int r0 = mw + mt * 16;
            a[mt][0] = __float_as_uint(As[r0 + g][k8 + tig]);
            a[mt][1] = __float_as_uint(As[r0 + g + 8][k8 + tig]);
            a[mt][2] = __float_as_uint(As[r0 + g][k8 + tig + 4]);
            a[mt][3] = __float_as_uint(As[r0 + g + 8][k8 + tig + 4]);
        }
        #pragma unroll
        for (int nt = 0; nt < 4; nt++) {
            int cn = nw + nt * 8;
            b[nt][0] = __float_as_uint(Bs[k8 + tig][cn + g]);
            b[nt][1] = __float_as_uint(Bs[k8 + tig + 4][cn + g]);
        }
        #pragma unroll
        for (int mt = 0; mt < 4; mt++)
            #pragma unroll
            for (int nt = 0; nt < 4; nt++)
                asm volatile(
                    "mma.sync.aligned.m16n8k8.row.col.f32.tf32.tf32.f32 "
                    "{%0,%1,%2,%3},{%4,%5,%6,%7},{%8,%9},{%0,%1,%2,%3};"
                    : "+f"(cf[mt][nt][0]), "+f"(cf[mt][nt][1]),
                      "+f"(cf[mt][nt][2]), "+f"(cf[mt][nt][3])
                    : "r"(a[mt][0]), "r"(a[mt][1]), "r"(a[mt][2]), "r"(a[mt][3]),
                      "r"(b[nt][0]), "r"(b[nt][1]));
    }

    if (colBase < 256) {
        // featb + el1/er1
        #pragma unroll
        for (int mt = 0; mt < 4; mt++) {
            int gr0 = rowBase + mw + mt * 16 + g;
            int gr1 = gr0 + 8;
            #pragma unroll
            for (int nt = 0; nt < 4; nt++) {
                int col = colBase + nw + nt * 8 + tig * 2;
                if (gr0 < Nn) {
                    __nv_bfloat162 p = __floats2bfloat162_rn(cf[mt][nt][0], cf[mt][nt][1]);
                    *(__nv_bfloat162*)&g_featb[gr0 * F + col] = p;
                }
                if (gr1 < Nn) {
                    __nv_bfloat162 p = __floats2bfloat162_rn(cf[mt][nt][2], cf[mt][nt][3]);
                    *(__nv_bfloat162*)&g_featb[gr1 * F + col] = p;
                }
            }
        }
        int hid = (colBase + nw) >> 5;
        float alv[4][2], arv[4][2];
        #pragma unroll
        for (int nt = 0; nt < 4; nt++) {
            int col = colBase + nw + nt * 8 + tig * 2;
            alv[nt][0] = al1[col]; alv[nt][1] = al1[col + 1];
            arv[nt][0] = ar1[col]; arv[nt][1] = ar1[col + 1];
        }
        #pragma unroll
        for (int mt = 0; mt < 4; mt++) {
            float el0 = 0.f, el1v = 0.f, er0 = 0.f, er1v = 0.f;
            #pragma unroll
            for (int nt = 0; nt < 4; nt++) {
                el0  += cf[mt][nt][0] * alv[nt][0] + cf[mt][nt][1] * alv[nt][1];
                el1v += cf[mt][nt][2] * alv[nt][0] + cf[mt][nt][3] * alv[nt][1];
                er0  += cf[mt][nt][0] * arv[nt][0] + cf[mt][nt][1] * arv[nt][1];
                er1v += cf[mt][nt][2] * arv[nt][0] + cf[mt][nt][3] * arv[nt][1];
            }
            el0  += __shfl_xor_sync(0xffffffffu, el0, 1);  el0  += __shfl_xor_sync(0xffffffffu, el0, 2);
            el1v += __shfl_xor_sync(0xffffffffu, el1v, 1); el1v += __shfl_xor_sync(0xffffffffu, el1v, 2);
            er0  += __shfl_xor_sync(0xffffffffu, er0, 1);  er0  += __shfl_xor_sync(0xffffffffu, er0, 2);
            er1v += __shfl_xor_sync(0xffffffffu, er1v, 1); er1v += __shfl_xor_sync(0xffffffffu, er1v, 2);
            if (tig == 0) {
                int gr0 = rowBase + mw + mt * 16 + g;
                int gr1 = gr0 + 8;
                if (gr0 < Nn) { g_el[gr0 * Hh + hid] = el0;  g_er[gr0 * Hh + hid] = er0; }
                if (gr1 < Nn) { g_el[gr1 * Hh + hid] = el1v; g_er[gr1 * Hh + hid] = er1v; }
            }
        }
    } else {
        // residual base: g_base = b1 + x@resW1
        #pragma unroll
        for (int mt = 0; mt < 4; mt++) {
            int gr0 = rowBase + mw + mt * 16 + g;
            int gr1 = gr0 + 8;
            #pragma unroll
            for (int nt = 0; nt < 4; nt++) {
                int j = colBase - 256 + nw + nt * 8 + tig * 2;
                float bj0 = b1[j], bj1 = b1[j + 1];
                if (gr0 < Nn) {
                    float2 v = make_float2(cf[mt][nt][0] + bj0, cf[mt][nt][1] + bj1);
                    *(float2*)&g_base[gr0 * F + j] = v;
                }
                if (gr1 < Nn) {
                    float2 v = make_float2(cf[mt][nt][2] + bj0, cf[mt][nt][3] + bj1);
                    *(float2*)&g_base[gr1 * F + j] = v;
                }
            }
        }
    }
}

// ---------------- layer 1: fused softmax + gather aggregation + ELU ----------------
__global__ void agg1_kernel() {
    int n = blockIdx.x;
    int t = threadIdx.x;          // 0..63
    int h = t >> 3;
    float er_h = g_er[n * Hh + h];
    int start = g_rowptr[n];
    int end   = g_rowptr[n + 1];

    float ax = 0.f, ay = 0.f, az = 0.f, aw = 0.f;
    float ssum = 0.f;
    #pragma unroll 4
    for (int e = start; e < end; e++) {
        int s = g_csrc[e];
        float v = g_el[s * Hh + h] + er_h;
        v = v > 0.f ? v : ALPHA * v;
        float ex = __expf(v);
        ssum += ex;
        uint2 u = *(const uint2*)&g_featb[s * F + t * 4];
        float2 f01 = __bfloat1622float2(*reinterpret_cast<const __nv_bfloat162*>(&u.x));
        float2 f23 = __bfloat1622float2(*reinterpret_cast<const __nv_bfloat162*>(&u.y));
        ax = fmaf(ex, f01.x, ax);
        ay = fmaf(ex, f01.y, ay);
        az = fmaf(ex, f23.x, az);
        aw = fmaf(ex, f23.y, aw);
    }
    float inv = 1.f / fmaxf(ssum, 1e-9f);

    float4 base = *(const float4*)&g_base[n * F + t * 4];
    float rx = base.x + ax * inv;
    float ry = base.y + ay * inv;
    float rz = base.z + az * inv;
    float rw = base.w + aw * inv;
    rx = rx > 0.f ? rx : (__expf(rx) - 1.f);
    ry = ry > 0.f ? ry : (__expf(ry) - 1.f);
    rz = rz > 0.f ? rz : (__expf(rz) - 1.f);
    rw = rw > 0.f ? rw : (__expf(rw) - 1.f);
    *(float4*)&g_h1[n * F + t * 4] = make_float4(rx, ry, rz, rw);
}

// ---------------- layer 2: fused agg + head-mean + gated readout atomics ----------------
__global__ void agg2_kernel(const float* __restrict__ b2,
                            const int* __restrict__ graph_ids,
                            const float* __restrict__ Ww,
                            const float* __restrict__ bw) {
    int n = blockIdx.x;
    int t = threadIdx.x;          // 0..63
    int h = t >> 3;
    float er_h = g_er[n * Hh + h];
    int start = g_rowptr[n];
    int end   = g_rowptr[n + 1];

    float ax = 0.f, ay = 0.f, az = 0.f, aw = 0.f;
    float ssum = 0.f;
    #pragma unroll 4
    for (int e = start; e < end; e++) {
        int s = g_csrc[e];
        float v = g_el[s * Hh + h] + er_h;
        v = v > 0.f ? v : ALPHA * v;
        float ex = __expf(v);
        ssum += ex;
        uint2 u = *(const uint2*)&g_featb[s * F + t * 4];
        float2 f01 = __bfloat1622float2(*reinterpret_cast<const __nv_bfloat162*>(&u.x));
        float2 f23 = __bfloat1622float2(*reinterpret_cast<const __nv_bfloat162*>(&u.y));
        ax = fmaf(ex, f01.x, ax);
        ay = fmaf(ex, f01.y, ay);
        az = fmaf(ex, f23.x, az);
        aw = fmaf(ex, f23.y, aw);
    }
    float inv = 1.f / fmaxf(ssum, 1e-9f);

    float4 hb = *(const float4*)&g_h1[n * F + t * 4];
    float4 bb = *(const float4*)&b2[t * 4];
    float rx = hb.x + bb.x + ax * inv;
    float ry = hb.y + bb.y + ay * inv;
    float rz = hb.z + bb.z + az * inv;
    float rw = hb.w + bb.w + aw * inv;

    rx += __shfl_xor_sync(0xffffffffu, rx, 8);  ry += __shfl_xor_sync(0xffffffffu, ry, 8);
    rz += __shfl_xor_sync(0xffffffffu, rz, 8);  rw += __shfl_xor_sync(0xffffffffu, rw, 8);
    rx += __shfl_xor_sync(0xffffffffu, rx, 16); ry += __shfl_xor_sync(0xffffffffu, ry, 16);
    rz += __shfl_xor_sync(0xffffffffu, rz, 16); rw += __shfl_xor_sync(0xffffffffu, rw, 16);

    __shared__ float sh[2][8][4];
    int warp = t >> 5;
    if ((t & 31) < 8) {
        sh[warp][t & 7][0] = rx; sh[warp][t & 7][1] = ry;
        sh[warp][t & 7][2] = rz; sh[warp][t & 7][3] = rw;
    }
    __syncthreads();

    if (t < 32) {
        float h0 = 0.f, h1v = 0.f, h2v = 0.f, h3 = 0.f, partial = 0.f;
        if (t < 8) {
            h0  = (sh[0][t][0] + sh[1][t][0]) * 0.125f;
            h1v = (sh[0][t][1] + sh[1][t][1]) * 0.125f;
            h2v = (sh[0][t][2] + sh[1][t][2]) * 0.125f;
            h3  = (sh[0][t][3] + sh[1][t][3]) * 0.125f;
            float4 wv = *(const float4*)&Ww[t * 4];
            partial = h0 * wv.x + h1v * wv.y + h2v * wv.z + h3 * wv.w;
        }
        #pragma unroll
        for (int o = 4; o > 0; o >>= 1) partial += __shfl_down_sync(0xffffffffu, partial, o);
        float w = 0.f;
        if (t == 0) w = 1.f / (1.f + __expf(-(partial + bw[0])));
        w = __shfl_sync(0xffffffffu, w, 0);
        if (t < 8) {
            int gid = graph_ids[n];
            float* gs = &g_gsum[gid * Dd + t * 4];
            float* gm = &g_gmax[gid * Dd + t * 4];
            atomicAdd(gs + 0, w * h0);  atomicMaxFloat(gm + 0, h0);
            atomicAdd(gs + 1, w * h1v); atomicMaxFloat(gm + 1, h1v);
            atomicAdd(gs + 2, w * h2v); atomicMaxFloat(gm + 2, h2v);
            atomicAdd(gs + 3, w * h3);  atomicMaxFloat(gm + 3, h3);
        }
    }
}

// ======= layer-2 tf32 GEMM: featb=bf16(h1@W2) + fused el2/er2 epilogue =======
#define TBM 128
#define TBN 128
#define TBK 32
__global__ void gemm2_tc_kernel(const float* __restrict__ A, const float* __restrict__ B,
                                const float* __restrict__ al2, const float* __restrict__ ar2) {
    __shared__ float As[TBM][TBK + 4];
    __shared__ float Bs[TBK][TBN + 4];
    int tid = threadIdx.x;
    int lane = tid & 31, warp = tid >> 5;
    int g = lane >> 2, tig = lane & 3;
    int mw = (warp & 1) * 64;
    int nw = (warp >> 1) * 32;
    int rowBase = blockIdx.y * TBM;
    int colBase = blockIdx.x * TBN;

    float cf[4][4][4];
    #pragma unroll
    for (int mt = 0; mt < 4; mt++)
        #pragma unroll
        for (int nt = 0; nt < 4; nt++)
            #pragma unroll
            for (int q = 0; q < 4; q++) cf[mt][nt][q] = 0.f;

    for (int k0 = 0; k0 < F; k0 += TBK) {
        #pragma unroll
        for (int i = 0; i < 4; i++) {
            int id = tid + i * 256;
            int r = id >> 3, c4 = (id & 7) * 4;
            int gr = rowBase + r;
            float4 v = (gr < Nn) ? *(const float4*)&A[gr * F + k0 + c4]
                                 : make_float4(0.f, 0.f, 0.f, 0.f);
            uint4 u;
            u.x = f2tf32(v.x); u.y = f2tf32(v.y); u.z = f2tf32(v.z); u.w = f2tf32(v.w);
            *(uint4*)&As[r][c4] = u;
        }
        #pragma unroll
        for (int i = 0; i < 4; i++) {
            int id = tid + i * 256;
            int r = id >> 5, c4 = (id & 31) * 4;
            float4 v = *(const float4*)&B[(k0 + r) * F + colBase + c4];
            uint4 u;
            u.x = f2tf32(v.x); u.y = f2tf32(v.y); u.z = f2tf32(v.z); u.w = f2tf32(v.w);
            *(uint4*)&Bs[r][c4] = u;
        }
        __syncthreads();
        #pragma unroll
        for (int k8 = 0; k8 < TBK; k8 += 8) {
            unsigned a[4][4], b[4][2];
            #pragma unroll
            for (int mt = 0; mt < 4; mt++) {
                int r0 = mw + mt * 16;
                a[mt][0] = __float_as_uint(As[r0 + g][k8 + tig]);
                a[mt][1] = __float_as_uint(As[r0 + g + 8][k8 + tig]);
                a[mt][2] = __float_as_uint(As[r0 + g][k8 + tig + 4]);
                a[mt][3] = __float_as_uint(As[r0 + g + 8][k8 + tig + 4]);
            }
            #pragma unroll
            for (int nt = 0; nt < 4; nt++) {
                int cn = nw + nt * 8;
                b[nt][0] = __float_as_uint(Bs[k8 + tig][cn + g]);
                b[nt][1] = __float_as_uint(Bs[k8 + tig + 4][cn + g]);
            }
            #pragma unroll
            for (int mt = 0; mt < 4; mt++)
                #pragma unroll
                for (int nt = 0; nt < 4; nt++)
                    asm volatile(
                        "mma.sync.aligned.m16n8k8.row.col.f32.tf32.tf32.f32 "
                        "{%0,%1,%2,%3},{%4,%5,%6,%7},{%8,%9},{%0,%1,%2,%3};"
                        : "+f"(cf[mt][nt][0]), "+f"(cf[mt][nt][1]),
                          "+f"(cf[mt][nt][2]), "+f"(cf[mt][nt][3])
                        : "r"(a[mt][0]), "r"(a[mt][1]), "r"(a[mt][2]), "r"(a[mt][3]),
                          "r"(b[nt][0]), "r"(b[nt][1]));
        }
        __syncthreads();
    }

    // epilogue: bf16 featb stores + el2/er2 (warp tile = one head)
    #pragma unroll
    for (int mt = 0; mt < 4; mt++) {
        int gr0 = rowBase + mw + mt * 16 + g;
        int gr1 = gr0 + 8;
        #pragma unroll
        for (int nt = 0; nt < 4; nt++) {
            int col = colBase + nw + nt * 8 + tig * 2;
            if (gr0 < Nn) {
                __nv_bfloat162 p = __floats2bfloat162_rn(cf[mt][nt][0], cf[mt][nt][1]);
                *(__nv_bfloat162*)&g_featb[gr0 * F + col] = p;
            }
            if (gr1 < Nn) {
                __nv_bfloat162 p = __floats2bfloat162_rn(cf[mt][nt][2], cf[mt][nt][3]);
                *(__nv_bfloat162*)&g_featb[gr1 * F + col] = p;
            }
        }
    }
    int hid = (colBase + nw) >> 5;
    float alv[4][2], arv[4][2];
    #pragma unroll
    for (int nt = 0; nt < 4; nt++) {
        int col = colBase + nw + nt * 8 + tig * 2;
        alv[nt][0] = al2[col]; alv[nt][1] = al2[col + 1];
        arv[nt][0] = ar2[col]; arv[nt][1] = ar2[col + 1];
    }
    #pragma unroll
    for (int mt = 0; mt < 4; mt++) {
        float el0 = 0.f, el1v = 0.f, er0 = 0.f, er1v = 0.f;
        #pragma unroll
        for (int nt = 0; nt < 4; nt++) {
            el0  += cf[mt][nt][0] * alv[nt][0] + cf[mt][nt][1] * alv[nt][1];
            el1v += cf[mt][nt][2] * alv[nt][0] + cf[mt][nt][3] * alv[nt][1];
            er0  += cf[mt][nt][0] * arv[nt][0] + cf[mt][nt][1] * arv[nt][1];
            er1v += cf[mt][nt][2] * arv[nt][0] + cf[mt][nt][3] * arv[nt][1];
        }
        el0  += __shfl_xor_sync(0xffffffffu, el0, 1);  el0  += __shfl_xor_sync(0xffffffffu, el0, 2);
        el1v += __shfl_xor_sync(0xffffffffu, el1v, 1); el1v += __shfl_xor_sync(0xffffffffu, el1v, 2);
        er0  += __shfl_xor_sync(0xffffffffu, er0, 1);  er0  += __shfl_xor_sync(0xffffffffu, er0, 2);
        er1v += __shfl_xor_sync(0xffffffffu, er1v, 1); er1v += __shfl_xor_sync(0xffffffffu, er1v, 2);
        if (tig == 0) {
            int gr0 = rowBase + mw + mt * 16 + g;
            int gr1 = gr0 + 8;
            if (gr0 < Nn) { g_el[gr0 * Hh + hid] = el0;  g_er[gr0 * Hh + hid] = er0; }
            if (gr1 < Nn) { g_el[gr1 * Hh + hid] = el1v; g_er[gr1 * Hh + hid] = er1v; }
        }
    }
}

// ---------------- MLP head ----------------
__global__ void mlp_kernel(const float* __restrict__ Wp1, const float* __restrict__ bp1,
                           const float* __restrict__ gamma, const float* __restrict__ beta,
                           const float* __restrict__ rm, const float* __restrict__ rv,
                           const float* __restrict__ Wp2, const float* __restrict__ bp2,
                           float* __restrict__ out) {
    int g = blockIdx.x;
    int t = threadIdx.x;      // 0..127
    __shared__ float gv[2 * Dd];
    __shared__ float red[HID];
    if (t < Dd) gv[t] = g_gsum[g * Dd + t];
    else if (t < 2 * Dd) {
        float mv = g_gmax[g * Dd + (t - Dd)];
        gv[t] = isfinite(mv) ? mv : 0.f;
    }
    __syncthreads();
    float acc = bp1[t];
    #pragma unroll
    for (int k = 0; k < 2 * Dd; k++) acc = fmaf(gv[k], Wp1[k * HID + t], acc);
    acc = fmaxf(acc, 0.f);
    acc = (acc - rm[t]) * rsqrtf(rv[t] + BN_EPS) * gamma[t] + beta[t];
    red[t] = acc * Wp2[t];
    __syncthreads();
    for (int s = 64; s > 0; s >>= 1) {
        if (t < s) red[t] += red[t + s];
        __syncthreads();
    }
    if (t == 0) out[g] = red[0] + bp2[0];
}

// ---------------- launch ----------------
extern "C" void kernel_launch(void* const* d_in, const int* in_sizes, int n_in,
                              void* d_out, int out_size) {
    const float* x     = (const float*)d_in[0];
    const int*   src   = (const int*)  d_in[1];
    const int*   dst   = (const int*)  d_in[2];
    const int*   gids  = (const int*)  d_in[3];
    const float* W1    = (const float*)d_in[4];
    const float* al1   = (const float*)d_in[5];
    const float* ar1   = (const float*)d_in[6];
    const float* b1    = (const float*)d_in[7];
    const float* resW1 = (const float*)d_in[8];
    const float* W2    = (const float*)d_in[9];
    const float* al2   = (const float*)d_in[10];
    const float* ar2   = (const float*)d_in[11];
    const float* b2    = (const float*)d_in[12];
    const float* Ww    = (const float*)d_in[13];
    const float* bw    = (const float*)d_in[14];
    const float* Wp1   = (const float*)d_in[15];
    const float* bp1   = (const float*)d_in[16];
    const float* gamma = (const float*)d_in[17];
    const float* beta  = (const float*)d_in[18];
    const float* rm    = (const float*)d_in[19];
    const float* rv    = (const float*)d_in[20];
    const float* Wp2   = (const float*)d_in[21];
    const float* bp2   = (const float*)d_in[22];
    float* out = (float*)d_out;

    int* pcnt;  cudaGetSymbolAddress((void**)&pcnt, g_cnt);
    float* pgs; cudaGetSymbolAddress((void**)&pgs, g_gsum);
    float* pgm; cudaGetSymbolAddress((void**)&pgm, g_gmax);
    float* ph1; cudaGetSymbolAddress((void**)&ph1, g_h1);

    static cudaStream_t s2 = nullptr;
    static cudaEvent_t e1 = nullptr, e2 = nullptr;
    if (!s2) {
        cudaStreamCreateWithFlags(&s2, cudaStreamNonBlocking);
        cudaEventCreateWithFlags(&e1, cudaEventDisableTiming);
        cudaEventCreateWithFlags(&e2, cudaEventDisableTiming);
    }

    const float NEG_INF = -INFINITY;
    const int NB = (Nn + 255) / 256;

    cudaEventRecord(e1, 0);
    cudaStreamWaitEvent(s2, e1, 0);

    // ===== side stream: CSR build + readout-accumulator fills =====
    fill_int_kernel<<<NB, 256, 0, s2>>>(pcnt, Nn, 0);
    hist_kernel<<<(Ee + 255) / 256, 256, 0, s2>>>(dst);
    scan1_kernel<<<NB, 256, 0, s2>>>();
    scan2_kernel<<<1, 256, 0, s2>>>(NB);
    scan3_kernel<<<NB, 256, 0, s2>>>();
    scatter_kernel<<<(Ee + 255) / 256, 256, 0, s2>>>(src, dst);
    fill_kernel<<<(Gg * Dd + 255) / 256, 256, 0, s2>>>(pgs, Gg * Dd, 0.f);
    fill_kernel<<<(Gg * Dd + 255) / 256, 256, 0, s2>>>(pgm, Gg * Dd, NEG_INF);
    cudaEventRecord(e2, s2);

    // ===== main stream: layer 1 tensor-core projection (overlaps CSR build) =====
    {
        dim3 grid(4, (Nn + 127) / 128);
        node1_tc_kernel<<<grid, 256>>>(x, W1, resW1, b1, al1, ar1);
    }

    cudaStreamWaitEvent(0, e2, 0);
    agg1_kernel<<<Nn, 64>>>();

    // ===== layer 2 =====
    {
        dim3 grid(F / TBN, (Nn + TBM - 1) / TBM);
        gemm2_tc_kernel<<<grid, 256>>>(ph1, W2, al2, ar2);
    }
    agg2_kernel<<<Nn, 64>>>(b2, gids, Ww, bw);

    // ===== MLP =====
    mlp_kernel<<<Gg, HID>>>(Wp1, bp1, gamma, beta, rm, rv, Wp2, bp2, out);
}